// round 9
// baseline (speedup 1.0000x reference)
#include <cuda_runtime.h>
#include <cuda_bf16.h>
#include <math.h>
#include <stdint.h>

#define BB 8
#define SS 2048
#define DD 768

// ---------------------------------------------------------------------------
// Scratch (device globals: allocation-free per harness rules)
// ---------------------------------------------------------------------------
__device__ __nv_bfloat16 g_xhi[BB * SS * DD], g_xlo[BB * SS * DD];
__device__ __nv_bfloat16 g_Wqhi[DD * DD], g_Wqlo[DD * DD];
__device__ __nv_bfloat16 g_Wkhi[DD * DD], g_Wklo[DD * DD];
__device__ __nv_bfloat16 g_Wvhi[DD * DD], g_Wvlo[DD * DD];
__device__ __nv_bfloat16 g_Wphi[DD * DD], g_Wplo[DD * DD];
__device__ __nv_bfloat16 g_Qhi[BB * SS * DD], g_Qlo[BB * SS * DD];
__device__ __nv_bfloat16 g_Khi[BB * SS * DD], g_Klo[BB * SS * DD];
__device__ float         g_V[BB * SS * DD];
__device__ __nv_bfloat16 g_Vthi[BB * DD * SS], g_Vtlo[BB * DD * SS];
__device__ float         g_P[(size_t)BB * SS * SS];
__device__ __nv_bfloat16 g_Phi[(size_t)BB * SS * SS], g_Plo[(size_t)BB * SS * SS];
__device__ __nv_bfloat16 g_Ohi[BB * SS * DD], g_Olo[BB * SS * DD];

// ---------------------------------------------------------------------------
// Portable PTX helpers (no 'a'-gated features: ldmatrix / mma.sync / cp.async)
// ---------------------------------------------------------------------------
__device__ __forceinline__ uint32_t smem_to_u32(const void* p) {
    uint32_t a;
    asm("{ .reg .u64 t; cvta.to.shared.u64 t, %1; cvt.u32.u64 %0, t; }"
        : "=r"(a) : "l"(p));
    return a;
}

#define CP_ASYNC16(saddr, gaddr) \
    asm volatile("cp.async.cg.shared.global [%0], [%1], 16;" :: "r"(saddr), "l"(gaddr))
#define CP_COMMIT() asm volatile("cp.async.commit_group;" ::: "memory")
#define CP_WAIT(N)  asm volatile("cp.async.wait_group %0;" :: "n"(N) : "memory")

__device__ __forceinline__ void ldm_x4(uint32_t* r, uint32_t addr) {
    asm volatile("ldmatrix.sync.aligned.m8n8.x4.shared.b16 {%0,%1,%2,%3}, [%4];"
                 : "=r"(r[0]), "=r"(r[1]), "=r"(r[2]), "=r"(r[3]) : "r"(addr));
}

__device__ __forceinline__ void mma_bf16(float* c, const uint32_t* a,
                                         uint32_t b0, uint32_t b1) {
    asm volatile(
        "mma.sync.aligned.m16n8k16.row.col.f32.bf16.bf16.f32 "
        "{%0,%1,%2,%3}, {%4,%5,%6,%7}, {%8,%9}, {%0,%1,%2,%3};"
        : "+f"(c[0]), "+f"(c[1]), "+f"(c[2]), "+f"(c[3])
        : "r"(a[0]), "r"(a[1]), "r"(a[2]), "r"(a[3]), "r"(b0), "r"(b1));
}

__device__ __forceinline__ uint32_t pack_bf2(float a, float b) {
    __nv_bfloat162 t(__float2bfloat16(a), __float2bfloat16(b));
    return *reinterpret_cast<uint32_t*>(&t);
}

// ---------------------------------------------------------------------------
// Split-bf16 HMMA GEMM (NT): C[M,N] = alpha*(A @ B^T) + bias
//   A[M,K], B[N,K], both K-contiguous. hi/lo pairs; acc = hh + hl + lh (fp32).
//   128x128 block tile, BK=32, 128 threads, 4 warps, warp tile 64x64.
//   2 CTAs/SM. grid = (N/128, M/128, batch).
// ---------------------------------------------------------------------------
#define ROWB 80                      // smem row pitch bytes (64B data + 16B pad)
#define MATB (128 * ROWB)            // 10240 B per matrix tile
#define STGB (4 * MATB)              // 40960 B per stage (Ah,Al,Bh,Bl)
#define GEMM_SMEM_BYTES (2 * STGB)   // 81920

__global__ __launch_bounds__(128, 2) void mma_gemm(
    const __nv_bfloat16* __restrict__ Ahi, const __nv_bfloat16* __restrict__ Alo,
    const __nv_bfloat16* __restrict__ Bhi, const __nv_bfloat16* __restrict__ Blo,
    const float* __restrict__ bias, float alpha,
    float* __restrict__ Cf,
    __nv_bfloat16* __restrict__ Chi, __nv_bfloat16* __restrict__ Clo,
    int ldc, int K, size_t strA, size_t strB, size_t strC)
{
    extern __shared__ char smem[];
    const uint32_t sb = smem_to_u32(smem);

    const int tid = threadIdx.x;
    const int wid = tid >> 5;
    const int lid = tid & 31;
    const int bm = blockIdx.y << 7;
    const int bn = blockIdx.x << 7;
    const int wm = (wid & 1) << 6;   // warp row offset (0,64)
    const int wn = (wid >> 1) << 6;  // warp col offset (0,64)

    Ahi += blockIdx.z * strA; Alo += blockIdx.z * strA;
    Bhi += blockIdx.z * strB; Blo += blockIdx.z * strB;

    // ---- global->smem copy: thread t owns row t (64B = 4x cp.async16) ----
    const uint32_t soff = (uint32_t)tid * ROWB;

    auto issue_stage = [&](int c, int stg) {
        const int k0 = c << 5;
        const uint32_t s0 = sb + stg * STGB + soff;
        const __nv_bfloat16* gA  = Ahi + (size_t)(bm + tid) * K + k0;
        const __nv_bfloat16* gAl = Alo + (size_t)(bm + tid) * K + k0;
        const __nv_bfloat16* gB  = Bhi + (size_t)(bn + tid) * K + k0;
        const __nv_bfloat16* gBl = Blo + (size_t)(bn + tid) * K + k0;
        #pragma unroll
        for (int u = 0; u < 4; u++) {
            CP_ASYNC16(s0 + 0 * MATB + u * 16, gA + u * 8);
            CP_ASYNC16(s0 + 1 * MATB + u * 16, gAl + u * 8);
            CP_ASYNC16(s0 + 2 * MATB + u * 16, gB + u * 8);
            CP_ASYNC16(s0 + 3 * MATB + u * 16, gBl + u * 8);
        }
    };

    // ---- ldmatrix lane addressing ----
    // A (16x16 tile): row = (l&15), colByte = (l>>4)*16
    const uint32_t aLane = (uint32_t)(wm + (lid & 15)) * ROWB + ((lid >> 4) << 4);
    // B (n16 x k16): row = (l&7) + ((l>>4)<<3), colByte = ((l>>3)&1)*16
    const uint32_t bLane = (uint32_t)(wn + (lid & 7) + ((lid >> 4) << 3)) * ROWB
                           + (((lid >> 3) & 1) << 4);

    float acc[4][8][4];
    #pragma unroll
    for (int i = 0; i < 4; i++)
        #pragma unroll
        for (int j = 0; j < 8; j++)
            #pragma unroll
            for (int q = 0; q < 4; q++) acc[i][j][q] = 0.0f;

    const int nch = K >> 5;
    issue_stage(0, 0);
    CP_COMMIT();

    for (int c = 0; c < nch; c++) {
        if (c + 1 < nch) {
            issue_stage(c + 1, (c + 1) & 1);
            CP_COMMIT();
            CP_WAIT(1);
        } else {
            CP_WAIT(0);
        }
        __syncthreads();

        const uint32_t stg = sb + (c & 1) * STGB;
        #pragma unroll
        for (int ks = 0; ks < 2; ks++) {
            const uint32_t kb = ks << 5;   // 32B per k16
            uint32_t aH[4][4], aL[4][4], bF[4][4];
            // load A-hi (4 m16-tiles), A-lo, B-hi (4 n16-tiles)
            #pragma unroll
            for (int mt = 0; mt < 4; mt++)
                ldm_x4(aH[mt], stg + 0 * MATB + aLane + mt * (16 * ROWB) + kb);
            #pragma unroll
            for (int mt = 0; mt < 4; mt++)
                ldm_x4(aL[mt], stg + 1 * MATB + aLane + mt * (16 * ROWB) + kb);
            #pragma unroll
            for (int g = 0; g < 4; g++)
                ldm_x4(bF[g], stg + 2 * MATB + bLane + g * (16 * ROWB) + kb);
            // hh
            #pragma unroll
            for (int mt = 0; mt < 4; mt++)
                #pragma unroll
                for (int g = 0; g < 4; g++) {
                    mma_bf16(acc[mt][2 * g],     aH[mt], bF[g][0], bF[g][1]);
                    mma_bf16(acc[mt][2 * g + 1], aH[mt], bF[g][2], bF[g][3]);
                }
            // lh (B-hi still resident)
            #pragma unroll
            for (int mt = 0; mt < 4; mt++)
                #pragma unroll
                for (int g = 0; g < 4; g++) {
                    mma_bf16(acc[mt][2 * g],     aL[mt], bF[g][0], bF[g][1]);
                    mma_bf16(acc[mt][2 * g + 1], aL[mt], bF[g][2], bF[g][3]);
                }
            // load B-lo into same frag regs, then hl
            #pragma unroll
            for (int g = 0; g < 4; g++)
                ldm_x4(bF[g], stg + 3 * MATB + bLane + g * (16 * ROWB) + kb);
            #pragma unroll
            for (int mt = 0; mt < 4; mt++)
                #pragma unroll
                for (int g = 0; g < 4; g++) {
                    mma_bf16(acc[mt][2 * g],     aH[mt], bF[g][0], bF[g][1]);
                    mma_bf16(acc[mt][2 * g + 1], aH[mt], bF[g][2], bF[g][3]);
                }
        }
        __syncthreads();
    }

    // ---- epilogue ----
    const int r0 = lid >> 2;
    const int cq = (lid & 3) << 1;
    #pragma unroll
    for (int mt = 0; mt < 4; mt++) {
        #pragma unroll
        for (int half = 0; half < 2; half++) {
            const int row = bm + wm + mt * 16 + r0 + half * 8;
            const size_t base = blockIdx.z * strC + (size_t)row * ldc + bn + wn;
            #pragma unroll
            for (int nt = 0; nt < 8; nt++) {
                const int col = wn + nt * 8 + cq;
                float v0 = acc[mt][nt][half * 2]     * alpha;
                float v1 = acc[mt][nt][half * 2 + 1] * alpha;
                if (bias) {
                    v0 += __ldg(bias + bn + col);
                    v1 += __ldg(bias + bn + col + 1);
                }
                if (Cf)
                    __stcs(reinterpret_cast<float2*>(Cf + base + nt * 8 + cq),
                           make_float2(v0, v1));
                if (Chi) {
                    const __nv_bfloat16 h0 = __float2bfloat16(v0);
                    const __nv_bfloat16 h1 = __float2bfloat16(v1);
                    const float l0 = v0 - __bfloat162float(h0);
                    const float l1 = v1 - __bfloat162float(h1);
                    __nv_bfloat162 hp(h0, h1);
                    __nv_bfloat162 lp(__float2bfloat16(l0), __float2bfloat16(l1));
                    *reinterpret_cast<uint32_t*>(Chi + base + nt * 8 + cq) =
                        *reinterpret_cast<uint32_t*>(&hp);
                    *reinterpret_cast<uint32_t*>(Clo + base + nt * 8 + cq) =
                        *reinterpret_cast<uint32_t*>(&lp);
                }
            }
        }
    }
}

// ---------------------------------------------------------------------------
// fp32 -> bf16 hi/lo split (vectorized)
// ---------------------------------------------------------------------------
__global__ void split_kernel(const float* __restrict__ in,
                             __nv_bfloat16* __restrict__ hi,
                             __nv_bfloat16* __restrict__ lo, int n4)
{
    const int i = blockIdx.x * blockDim.x + threadIdx.x;
    if (i >= n4) return;
    const float4 v = reinterpret_cast<const float4*>(in)[i];
    float f[4] = {v.x, v.y, v.z, v.w};
    float l[4];
    #pragma unroll
    for (int j = 0; j < 4; j++) {
        const __nv_bfloat16 h = __float2bfloat16(f[j]);
        l[j] = f[j] - __bfloat162float(h);
    }
    reinterpret_cast<uint2*>(hi)[i] =
        make_uint2(pack_bf2(f[0], f[1]), pack_bf2(f[2], f[3]));
    reinterpret_cast<uint2*>(lo)[i] =
        make_uint2(pack_bf2(l[0], l[1]), pack_bf2(l[2], l[3]));
}

// ---------------------------------------------------------------------------
// V[B,S,D] fp32 -> Vt[B,D,S] bf16 hi/lo (32x32 SMEM tile transpose)
// ---------------------------------------------------------------------------
__global__ __launch_bounds__(256) void vtrans_split(const float* __restrict__ V,
                                                    __nv_bfloat16* __restrict__ Vth,
                                                    __nv_bfloat16* __restrict__ Vtl)
{
    __shared__ float t[32][33];
    const int b = blockIdx.z;
    const int s0 = blockIdx.x << 5, d0 = blockIdx.y << 5;
    const int tx = threadIdx.x & 31, ty = threadIdx.x >> 5;
    const float* Vb = V + (size_t)b * SS * DD;
    #pragma unroll
    for (int i = 0; i < 4; i++)
        t[ty + i * 8][tx] = Vb[(size_t)(s0 + ty + i * 8) * DD + d0 + tx];
    __syncthreads();
    __nv_bfloat16* th = Vth + (size_t)b * DD * SS;
    __nv_bfloat16* tl = Vtl + (size_t)b * DD * SS;
    #pragma unroll
    for (int i = 0; i < 4; i++) {
        const int d = d0 + ty + i * 8, s = s0 + tx;
        const float f = t[tx][ty + i * 8];
        const __nv_bfloat16 h = __float2bfloat16(f);
        th[(size_t)d * SS + s] = h;
        tl[(size_t)d * SS + s] = __float2bfloat16(f - __bfloat162float(h));
    }
}

// ---------------------------------------------------------------------------
// Row softmax over S=2048, emitting bf16 hi/lo of the result.
// ---------------------------------------------------------------------------
__global__ __launch_bounds__(256) void softmax_split(const float* __restrict__ P,
                                                     __nv_bfloat16* __restrict__ Phi,
                                                     __nv_bfloat16* __restrict__ Plo)
{
    const size_t rowoff = (size_t)blockIdx.x * SS;
    const float* row = P + rowoff;
    const int tid = threadIdx.x;
    __shared__ float red[8];

    float4 v0 = __ldcs(((const float4*)row) + tid);
    float4 v1 = __ldcs(((const float4*)row) + tid + 256);

    float m = fmaxf(fmaxf(fmaxf(v0.x, v0.y), fmaxf(v0.z, v0.w)),
                    fmaxf(fmaxf(v1.x, v1.y), fmaxf(v1.z, v1.w)));
    #pragma unroll
    for (int o = 16; o > 0; o >>= 1)
        m = fmaxf(m, __shfl_xor_sync(0xffffffffu, m, o));
    if ((tid & 31) == 0) red[tid >> 5] = m;
    __syncthreads();
    float bmax = red[0];
    #pragma unroll
    for (int i = 1; i < 8; i++) bmax = fmaxf(bmax, red[i]);
    __syncthreads();

    v0.x = __expf(v0.x - bmax); v0.y = __expf(v0.y - bmax);
    v0.z = __expf(v0.z - bmax); v0.w = __expf(v0.w - bmax);
    v1.x = __expf(v1.x - bmax); v1.y = __expf(v1.y - bmax);
    v1.z = __expf(v1.z - bmax); v1.w = __expf(v1.w - bmax);

    float s = v0.x + v0.y + v0.z + v0.w + v1.x + v1.y + v1.z + v1.w;
    #pragma unroll
    for (int o = 16; o > 0; o >>= 1)
        s += __shfl_xor_sync(0xffffffffu, s, o);
    if ((tid & 31) == 0) red[tid >> 5] = s;
    __syncthreads();
    float total = 0.0f;
    #pragma unroll
    for (int i = 0; i < 8; i++) total += red[i];
    const float inv = __frcp_rn(total);

    float f[8] = {v0.x * inv, v0.y * inv, v0.z * inv, v0.w * inv,
                  v1.x * inv, v1.y * inv, v1.z * inv, v1.w * inv};
    float l[8];
    #pragma unroll
    for (int j = 0; j < 8; j++) {
        const __nv_bfloat16 h = __float2bfloat16(f[j]);
        l[j] = f[j] - __bfloat162float(h);
    }
    uint2* ph = reinterpret_cast<uint2*>(Phi + rowoff);
    uint2* pl = reinterpret_cast<uint2*>(Plo + rowoff);
    ph[tid]       = make_uint2(pack_bf2(f[0], f[1]), pack_bf2(f[2], f[3]));
    ph[tid + 256] = make_uint2(pack_bf2(f[4], f[5]), pack_bf2(f[6], f[7]));
    pl[tid]       = make_uint2(pack_bf2(l[0], l[1]), pack_bf2(l[2], l[3]));
    pl[tid + 256] = make_uint2(pack_bf2(l[4], l[5]), pack_bf2(l[6], l[7]));
}

// ---------------------------------------------------------------------------
extern "C" void kernel_launch(void* const* d_in, const int* in_sizes, int n_in,
                              void* d_out, int out_size)
{
    const float* x  = (const float*)d_in[0];
    const float* Wq = (const float*)d_in[1];
    const float* bq = (const float*)d_in[2];
    const float* Wk = (const float*)d_in[3];
    const float* bk = (const float*)d_in[4];
    const float* Wv = (const float*)d_in[5];
    const float* bv = (const float*)d_in[6];
    const float* Wp = (const float*)d_in[7];
    const float* bp = (const float*)d_in[8];
    float* out = (float*)d_out;

    __nv_bfloat16 *xhi, *xlo, *Wqhi, *Wqlo, *Wkhi, *Wklo, *Wvhi, *Wvlo, *Wphi, *Wplo;
    __nv_bfloat16 *Qhi, *Qlo, *Khi, *Klo, *Vthi, *Vtlo, *Phi, *Plo, *Ohi, *Olo;
    float *V, *P;
    cudaGetSymbolAddress((void**)&xhi, g_xhi);   cudaGetSymbolAddress((void**)&xlo, g_xlo);
    cudaGetSymbolAddress((void**)&Wqhi, g_Wqhi); cudaGetSymbolAddress((void**)&Wqlo, g_Wqlo);
    cudaGetSymbolAddress((void**)&Wkhi, g_Wkhi); cudaGetSymbolAddress((void**)&Wklo, g_Wklo);
    cudaGetSymbolAddress((void**)&Wvhi, g_Wvhi); cudaGetSymbolAddress((void**)&Wvlo, g_Wvlo);
    cudaGetSymbolAddress((void**)&Wphi, g_Wphi); cudaGetSymbolAddress((void**)&Wplo, g_Wplo);
    cudaGetSymbolAddress((void**)&Qhi, g_Qhi);   cudaGetSymbolAddress((void**)&Qlo, g_Qlo);
    cudaGetSymbolAddress((void**)&Khi, g_Khi);   cudaGetSymbolAddress((void**)&Klo, g_Klo);
    cudaGetSymbolAddress((void**)&V, g_V);
    cudaGetSymbolAddress((void**)&Vthi, g_Vthi); cudaGetSymbolAddress((void**)&Vtlo, g_Vtlo);
    cudaGetSymbolAddress((void**)&P, g_P);
    cudaGetSymbolAddress((void**)&Phi, g_Phi);   cudaGetSymbolAddress((void**)&Plo, g_Plo);
    cudaGetSymbolAddress((void**)&Ohi, g_Ohi);   cudaGetSymbolAddress((void**)&Olo, g_Olo);

    cudaFuncSetAttribute(mma_gemm, cudaFuncAttributeMaxDynamicSharedMemorySize,
                         GEMM_SMEM_BYTES);

    const float alpha = 1.0f / sqrtf((float)DD);
    const size_t sQK = (size_t)SS * DD;
    const size_t sP  = (size_t)SS * SS;

    // split inputs
    {
        const int n4x = BB * SS * DD / 4;
        split_kernel<<<(n4x + 255) / 256, 256>>>(x, xhi, xlo, n4x);
        const int n4w = DD * DD / 4;
        split_kernel<<<(n4w + 255) / 256, 256>>>(Wq, Wqhi, Wqlo, n4w);
        split_kernel<<<(n4w + 255) / 256, 256>>>(Wk, Wkhi, Wklo, n4w);
        split_kernel<<<(n4w + 255) / 256, 256>>>(Wv, Wvhi, Wvlo, n4w);
        split_kernel<<<(n4w + 255) / 256, 256>>>(Wp, Wphi, Wplo, n4w);
    }

    const dim3 blk(128);
    const dim3 gproj(DD / 128, (BB * SS) / 128, 1);

    // Q = x@Wq^T + bq (emit bf16 hi/lo)
    mma_gemm<<<gproj, blk, GEMM_SMEM_BYTES>>>(xhi, xlo, Wqhi, Wqlo, bq, 1.0f,
                                              nullptr, Qhi, Qlo, DD, DD, 0, 0, 0);
    // K = x@Wk^T + bk
    mma_gemm<<<gproj, blk, GEMM_SMEM_BYTES>>>(xhi, xlo, Wkhi, Wklo, bk, 1.0f,
                                              nullptr, Khi, Klo, DD, DD, 0, 0, 0);
    // V = x@Wv^T + bv (fp32, then transpose-split)
    mma_gemm<<<gproj, blk, GEMM_SMEM_BYTES>>>(xhi, xlo, Wvhi, Wvlo, bv, 1.0f,
                                              V, nullptr, nullptr, DD, DD, 0, 0, 0);
    vtrans_split<<<dim3(SS / 32, DD / 32, BB), 256>>>(V, Vthi, Vtlo);

    // P = (Q@K^T)/sqrt(D) (fp32)
    mma_gemm<<<dim3(SS / 128, SS / 128, BB), blk, GEMM_SMEM_BYTES>>>(
        Qhi, Qlo, Khi, Klo, nullptr, alpha, P, nullptr, nullptr,
        SS, DD, sQK, sQK, sP);

    // softmax rows -> bf16 hi/lo
    softmax_split<<<BB * SS, 256>>>(P, Phi, Plo);

    // O = P@V (NT against Vt[D,S]; emit bf16 hi/lo)
    mma_gemm<<<dim3(DD / 128, SS / 128, BB), blk, GEMM_SMEM_BYTES>>>(
        Phi, Plo, Vthi, Vtlo, nullptr, 1.0f, nullptr, Ohi, Olo,
        DD, SS, sP, (size_t)DD * SS, sQK);

    // out = O@Wp^T + bp (fp32)
    mma_gemm<<<gproj, blk, GEMM_SMEM_BYTES>>>(Ohi, Olo, Wphi, Wplo, bp, 1.0f,
                                              out, nullptr, nullptr, DD, DD, 0, 0, 0);
}

// round 10
// speedup vs baseline: 2.0364x; 2.0364x over previous
#include <cuda_runtime.h>
#include <cuda_bf16.h>
#include <math.h>
#include <stdint.h>

#define BB 8
#define SS 2048
#define DD 768

// ---------------------------------------------------------------------------
// Scratch (device globals: allocation-free per harness rules)
// ---------------------------------------------------------------------------
__device__ __nv_bfloat16 g_xhi[BB * SS * DD], g_xlo[BB * SS * DD];
__device__ __nv_bfloat16 g_Wqhi[DD * DD], g_Wqlo[DD * DD];
__device__ __nv_bfloat16 g_Wkhi[DD * DD], g_Wklo[DD * DD];
__device__ __nv_bfloat16 g_Wvhi[DD * DD], g_Wvlo[DD * DD];
__device__ __nv_bfloat16 g_Wphi[DD * DD], g_Wplo[DD * DD];
__device__ __nv_bfloat16 g_Qhi[BB * SS * DD], g_Qlo[BB * SS * DD];
__device__ __nv_bfloat16 g_Khi[BB * SS * DD], g_Klo[BB * SS * DD];
__device__ __nv_bfloat16 g_Vthi[BB * DD * SS], g_Vtlo[BB * DD * SS];
__device__ float         g_P[(size_t)BB * SS * SS];
__device__ __nv_bfloat16 g_Phi[(size_t)BB * SS * SS], g_Plo[(size_t)BB * SS * SS];
__device__ __nv_bfloat16 g_Ohi[BB * SS * DD], g_Olo[BB * SS * DD];

// ---------------------------------------------------------------------------
// Portable PTX helpers (no 'a'-gated features: ldmatrix / mma.sync / cp.async)
// ---------------------------------------------------------------------------
__device__ __forceinline__ uint32_t smem_to_u32(const void* p) {
    uint32_t a;
    asm("{ .reg .u64 t; cvta.to.shared.u64 t, %1; cvt.u32.u64 %0, t; }"
        : "=r"(a) : "l"(p));
    return a;
}

#define CP_ASYNC16(saddr, gaddr) \
    asm volatile("cp.async.cg.shared.global [%0], [%1], 16;" :: "r"(saddr), "l"(gaddr))
#define CP_COMMIT() asm volatile("cp.async.commit_group;" ::: "memory")
#define CP_WAIT(N)  asm volatile("cp.async.wait_group %0;" :: "n"(N) : "memory")

__device__ __forceinline__ void ldm_x4(uint32_t* r, uint32_t addr) {
    asm volatile("ldmatrix.sync.aligned.m8n8.x4.shared.b16 {%0,%1,%2,%3}, [%4];"
                 : "=r"(r[0]), "=r"(r[1]), "=r"(r[2]), "=r"(r[3]) : "r"(addr));
}

__device__ __forceinline__ void mma_bf16(float* c, const uint32_t* a,
                                         uint32_t b0, uint32_t b1) {
    asm volatile(
        "mma.sync.aligned.m16n8k16.row.col.f32.bf16.bf16.f32 "
        "{%0,%1,%2,%3}, {%4,%5,%6,%7}, {%8,%9}, {%0,%1,%2,%3};"
        : "+f"(c[0]), "+f"(c[1]), "+f"(c[2]), "+f"(c[3])
        : "r"(a[0]), "r"(a[1]), "r"(a[2]), "r"(a[3]), "r"(b0), "r"(b1));
}

__device__ __forceinline__ uint32_t pack_bf2(float a, float b) {
    __nv_bfloat162 t(__float2bfloat16(a), __float2bfloat16(b));
    return *reinterpret_cast<uint32_t*>(&t);
}

// ---------------------------------------------------------------------------
// Shared GEMM-tile machinery (round-8 config: 256 thr, 8 warps, warp 32x64,
// 128x128 block tile, BK=32, double-buffered cp.async, 2 CTAs/SM)
// ---------------------------------------------------------------------------
#define ROWB 80                      // smem row pitch bytes (64B data + 16B pad)
#define MATB (128 * ROWB)            // 10240 B per matrix tile
#define STGB (4 * MATB)              // 40960 B per stage (Ah,Al,Bh,Bl)
#define GEMM_SMEM_BYTES (2 * STGB)   // 81920

struct MainloopOut { float acc[2][8][4]; };

// Runs the full K-loop; acc layout per round-8 fragment mapping.
__device__ __forceinline__ void gemm_mainloop(
    uint32_t sb, int tid,
    const __nv_bfloat16* Ahi, const __nv_bfloat16* Alo,
    const __nv_bfloat16* Bhi, const __nv_bfloat16* Blo,
    int bm, int bn, int K, float (*acc)[8][4])
{
    const int wid = tid >> 5;
    const int lid = tid & 31;
    const int wm = (wid & 3) << 5;
    const int wn = (wid >> 2) << 6;

    const int grow = tid >> 1;
    const int ghalf = (tid & 1) << 4;
    const uint32_t soff = grow * ROWB + ((tid & 1) << 5);

    auto issue_stage = [&](int c, int stg) {
        const int k0 = c << 5;
        const uint32_t s0 = sb + stg * STGB + soff;
        const __nv_bfloat16* gA  = Ahi + (size_t)(bm + grow) * K + k0 + ghalf;
        const __nv_bfloat16* gAl = Alo + (size_t)(bm + grow) * K + k0 + ghalf;
        const __nv_bfloat16* gB  = Bhi + (size_t)(bn + grow) * K + k0 + ghalf;
        const __nv_bfloat16* gBl = Blo + (size_t)(bn + grow) * K + k0 + ghalf;
        CP_ASYNC16(s0 + 0 * MATB,      gA);
        CP_ASYNC16(s0 + 0 * MATB + 16, gA + 8);
        CP_ASYNC16(s0 + 1 * MATB,      gAl);
        CP_ASYNC16(s0 + 1 * MATB + 16, gAl + 8);
        CP_ASYNC16(s0 + 2 * MATB,      gB);
        CP_ASYNC16(s0 + 2 * MATB + 16, gB + 8);
        CP_ASYNC16(s0 + 3 * MATB,      gBl);
        CP_ASYNC16(s0 + 3 * MATB + 16, gBl + 8);
    };

    const uint32_t aLane = (uint32_t)(wm + (lid & 15)) * ROWB + ((lid >> 4) << 4);
    const uint32_t bLane = (uint32_t)(wn + (lid & 7) + ((lid >> 4) << 3)) * ROWB
                           + (((lid >> 3) & 1) << 4);

    const int nch = K >> 5;
    issue_stage(0, 0);
    CP_COMMIT();

    for (int c = 0; c < nch; c++) {
        if (c + 1 < nch) {
            issue_stage(c + 1, (c + 1) & 1);
            CP_COMMIT();
            CP_WAIT(1);
        } else {
            CP_WAIT(0);
        }
        __syncthreads();

        const uint32_t stg = sb + (c & 1) * STGB;
        #pragma unroll
        for (int ks = 0; ks < 2; ks++) {
            const uint32_t kb = ks << 5;
            uint32_t aH[2][4], aL[2][4], bF[4][4];
            #pragma unroll
            for (int mt = 0; mt < 2; mt++)
                ldm_x4(aH[mt], stg + 0 * MATB + aLane + mt * (16 * ROWB) + kb);
            #pragma unroll
            for (int mt = 0; mt < 2; mt++)
                ldm_x4(aL[mt], stg + 1 * MATB + aLane + mt * (16 * ROWB) + kb);
            #pragma unroll
            for (int g = 0; g < 4; g++)
                ldm_x4(bF[g], stg + 2 * MATB + bLane + g * (16 * ROWB) + kb);
            // hh
            #pragma unroll
            for (int mt = 0; mt < 2; mt++)
                #pragma unroll
                for (int g = 0; g < 4; g++) {
                    mma_bf16(acc[mt][2 * g],     aH[mt], bF[g][0], bF[g][1]);
                    mma_bf16(acc[mt][2 * g + 1], aH[mt], bF[g][2], bF[g][3]);
                }
            // lh (B-hi resident)
            #pragma unroll
            for (int mt = 0; mt < 2; mt++)
                #pragma unroll
                for (int g = 0; g < 4; g++) {
                    mma_bf16(acc[mt][2 * g],     aL[mt], bF[g][0], bF[g][1]);
                    mma_bf16(acc[mt][2 * g + 1], aL[mt], bF[g][2], bF[g][3]);
                }
            // hl
            #pragma unroll
            for (int g = 0; g < 4; g++)
                ldm_x4(bF[g], stg + 3 * MATB + bLane + g * (16 * ROWB) + kb);
            #pragma unroll
            for (int mt = 0; mt < 2; mt++)
                #pragma unroll
                for (int g = 0; g < 4; g++) {
                    mma_bf16(acc[mt][2 * g],     aH[mt], bF[g][0], bF[g][1]);
                    mma_bf16(acc[mt][2 * g + 1], aH[mt], bF[g][2], bF[g][3]);
                }
        }
        __syncthreads();
    }
}

// ---------------------------------------------------------------------------
// Generic split-bf16 GEMM (NT): used for QK^T, P@Vt, out-projection.
// ---------------------------------------------------------------------------
__global__ __launch_bounds__(256, 2) void mma_gemm(
    const __nv_bfloat16* __restrict__ Ahi, const __nv_bfloat16* __restrict__ Alo,
    const __nv_bfloat16* __restrict__ Bhi, const __nv_bfloat16* __restrict__ Blo,
    const float* __restrict__ bias, float alpha,
    float* __restrict__ Cf,
    __nv_bfloat16* __restrict__ Chi, __nv_bfloat16* __restrict__ Clo,
    int ldc, int K, size_t strA, size_t strB, size_t strC)
{
    extern __shared__ char smem[];
    const uint32_t sb = smem_to_u32(smem);
    const int tid = threadIdx.x;
    const int wid = tid >> 5;
    const int lid = tid & 31;
    const int bm = blockIdx.y << 7;
    const int bn = blockIdx.x << 7;
    const int wm = (wid & 3) << 5;
    const int wn = (wid >> 2) << 6;

    float acc[2][8][4];
    #pragma unroll
    for (int i = 0; i < 2; i++)
        #pragma unroll
        for (int j = 0; j < 8; j++)
            #pragma unroll
            for (int q = 0; q < 4; q++) acc[i][j][q] = 0.0f;

    gemm_mainloop(sb, tid, Ahi + blockIdx.z * strA, Alo + blockIdx.z * strA,
                  Bhi + blockIdx.z * strB, Blo + blockIdx.z * strB,
                  bm, bn, K, acc);

    const int r0 = lid >> 2;
    const int cq = (lid & 3) << 1;
    #pragma unroll
    for (int mt = 0; mt < 2; mt++) {
        #pragma unroll
        for (int half = 0; half < 2; half++) {
            const int row = bm + wm + mt * 16 + r0 + half * 8;
            const size_t base = blockIdx.z * strC + (size_t)row * ldc + bn + wn;
            #pragma unroll
            for (int nt = 0; nt < 8; nt++) {
                const int col = wn + nt * 8 + cq;
                float v0 = acc[mt][nt][half * 2]     * alpha;
                float v1 = acc[mt][nt][half * 2 + 1] * alpha;
                if (bias) {
                    v0 += __ldg(bias + bn + col);
                    v1 += __ldg(bias + bn + col + 1);
                }
                if (Cf)
                    __stcs(reinterpret_cast<float2*>(Cf + base + nt * 8 + cq),
                           make_float2(v0, v1));
                if (Chi) {
                    const __nv_bfloat16 h0 = __float2bfloat16(v0);
                    const __nv_bfloat16 h1 = __float2bfloat16(v1);
                    const float l0 = v0 - __bfloat162float(h0);
                    const float l1 = v1 - __bfloat162float(h1);
                    __nv_bfloat162 hp(h0, h1);
                    __nv_bfloat162 lp(__float2bfloat16(l0), __float2bfloat16(l1));
                    *reinterpret_cast<uint32_t*>(Chi + base + nt * 8 + cq) =
                        *reinterpret_cast<uint32_t*>(&hp);
                    *reinterpret_cast<uint32_t*>(Clo + base + nt * 8 + cq) =
                        *reinterpret_cast<uint32_t*>(&lp);
                }
            }
        }
    }
}

// ---------------------------------------------------------------------------
// Fused QKV projection: z=0 -> Q(hi/lo), z=1 -> K(hi/lo),
// z=2 -> V emitted TRANSPOSED as Vt[b][d][s] hi/lo (via smem transpose).
// grid = (DD/128, BB*SS/128, 3)
// ---------------------------------------------------------------------------
__global__ __launch_bounds__(256, 2) void proj_qkv(
    const __nv_bfloat16* __restrict__ xhi, const __nv_bfloat16* __restrict__ xlo,
    const __nv_bfloat16* __restrict__ Wqh, const __nv_bfloat16* __restrict__ Wql,
    const __nv_bfloat16* __restrict__ Wkh, const __nv_bfloat16* __restrict__ Wkl,
    const __nv_bfloat16* __restrict__ Wvh, const __nv_bfloat16* __restrict__ Wvl,
    const float* __restrict__ bq, const float* __restrict__ bk,
    const float* __restrict__ bv,
    __nv_bfloat16* __restrict__ Qhi, __nv_bfloat16* __restrict__ Qlo,
    __nv_bfloat16* __restrict__ Khi, __nv_bfloat16* __restrict__ Klo,
    __nv_bfloat16* __restrict__ Vthi, __nv_bfloat16* __restrict__ Vtlo)
{
    extern __shared__ char smem[];
    const uint32_t sb = smem_to_u32(smem);
    const int tid = threadIdx.x;
    const int wid = tid >> 5;
    const int lid = tid & 31;
    const int bm = blockIdx.y << 7;
    const int bn = blockIdx.x << 7;
    const int wm = (wid & 3) << 5;
    const int wn = (wid >> 2) << 6;
    const int z = blockIdx.z;

    const __nv_bfloat16* Bh = (z == 0) ? Wqh : (z == 1) ? Wkh : Wvh;
    const __nv_bfloat16* Bl = (z == 0) ? Wql : (z == 1) ? Wkl : Wvl;
    const float* bias       = (z == 0) ? bq  : (z == 1) ? bk  : bv;

    float acc[2][8][4];
    #pragma unroll
    for (int i = 0; i < 2; i++)
        #pragma unroll
        for (int j = 0; j < 8; j++)
            #pragma unroll
            for (int q = 0; q < 4; q++) acc[i][j][q] = 0.0f;

    gemm_mainloop(sb, tid, xhi, xlo, Bh, Bl, bm, bn, DD, acc);

    const int r0 = lid >> 2;
    const int cq = (lid & 3) << 1;

    if (z < 2) {
        __nv_bfloat16* Chi = (z == 0) ? Qhi : Khi;
        __nv_bfloat16* Clo = (z == 0) ? Qlo : Klo;
        #pragma unroll
        for (int mt = 0; mt < 2; mt++) {
            #pragma unroll
            for (int half = 0; half < 2; half++) {
                const int row = bm + wm + mt * 16 + r0 + half * 8;
                const size_t base = (size_t)row * DD + bn + wn;
                #pragma unroll
                for (int nt = 0; nt < 8; nt++) {
                    const int col = wn + nt * 8 + cq;
                    float v0 = acc[mt][nt][half * 2]     + __ldg(bias + bn + col);
                    float v1 = acc[mt][nt][half * 2 + 1] + __ldg(bias + bn + col + 1);
                    const __nv_bfloat16 h0 = __float2bfloat16(v0);
                    const __nv_bfloat16 h1 = __float2bfloat16(v1);
                    const float l0 = v0 - __bfloat162float(h0);
                    const float l1 = v1 - __bfloat162float(h1);
                    __nv_bfloat162 hp(h0, h1);
                    __nv_bfloat162 lp(__float2bfloat16(l0), __float2bfloat16(l1));
                    *reinterpret_cast<uint32_t*>(Chi + base + nt * 8 + cq) =
                        *reinterpret_cast<uint32_t*>(&hp);
                    *reinterpret_cast<uint32_t*>(Clo + base + nt * 8 + cq) =
                        *reinterpret_cast<uint32_t*>(&lp);
                }
            }
        }
    } else {
        // V: write transposed tile via smem. sfT[col][row] (pitch 130 floats).
        float* sf = reinterpret_cast<float*>(smem);
        #pragma unroll
        for (int mt = 0; mt < 2; mt++) {
            #pragma unroll
            for (int half = 0; half < 2; half++) {
                const int rloc = wm + mt * 16 + r0 + half * 8;
                #pragma unroll
                for (int nt = 0; nt < 8; nt++) {
                    const int col = wn + nt * 8 + cq;
                    float v0 = acc[mt][nt][half * 2]     + __ldg(bias + bn + col);
                    float v1 = acc[mt][nt][half * 2 + 1] + __ldg(bias + bn + col + 1);
                    sf[(size_t)col * 130 + rloc]       = v0;
                    sf[(size_t)(col + 1) * 130 + rloc] = v1;
                }
            }
        }
        __syncthreads();
        // write Vt[b][bn+d][s_base + sc .. +63], hi/lo split on the fly
        const int b = bm >> 11;           // 2048 rows per batch; 128 | 2048
        const int s_base = bm & (SS - 1);
        const int d = tid >> 1;           // 0..127
        const int sc = (tid & 1) << 6;    // 0 / 64
        const float* srow = sf + (size_t)d * 130 + sc;
        __nv_bfloat16* th = Vthi + ((size_t)b * DD + bn + d) * SS + s_base + sc;
        __nv_bfloat16* tl = Vtlo + ((size_t)b * DD + bn + d) * SS + s_base + sc;
        #pragma unroll
        for (int j = 0; j < 64; j += 8) {
            uint4 ph, pl;
            uint32_t* php = reinterpret_cast<uint32_t*>(&ph);
            uint32_t* plp = reinterpret_cast<uint32_t*>(&pl);
            #pragma unroll
            for (int p = 0; p < 4; p++) {
                const float a = srow[j + 2 * p], c = srow[j + 2 * p + 1];
                const __nv_bfloat16 ha = __float2bfloat16(a);
                const __nv_bfloat16 hc = __float2bfloat16(c);
                __nv_bfloat162 hp2(ha, hc);
                __nv_bfloat162 lp2(__float2bfloat16(a - __bfloat162float(ha)),
                                   __float2bfloat16(c - __bfloat162float(hc)));
                php[p] = *reinterpret_cast<uint32_t*>(&hp2);
                plp[p] = *reinterpret_cast<uint32_t*>(&lp2);
            }
            *reinterpret_cast<uint4*>(th + j) = ph;
            *reinterpret_cast<uint4*>(tl + j) = pl;
        }
    }
}

// ---------------------------------------------------------------------------
// fp32 -> bf16 hi/lo split (vectorized)
// ---------------------------------------------------------------------------
__global__ void split_kernel(const float* __restrict__ in,
                             __nv_bfloat16* __restrict__ hi,
                             __nv_bfloat16* __restrict__ lo, int n4)
{
    const int i = blockIdx.x * blockDim.x + threadIdx.x;
    if (i >= n4) return;
    const float4 v = reinterpret_cast<const float4*>(in)[i];
    float f[4] = {v.x, v.y, v.z, v.w};
    float l[4];
    #pragma unroll
    for (int j = 0; j < 4; j++) {
        const __nv_bfloat16 h = __float2bfloat16(f[j]);
        l[j] = f[j] - __bfloat162float(h);
    }
    reinterpret_cast<uint2*>(hi)[i] =
        make_uint2(pack_bf2(f[0], f[1]), pack_bf2(f[2], f[3]));
    reinterpret_cast<uint2*>(lo)[i] =
        make_uint2(pack_bf2(l[0], l[1]), pack_bf2(l[2], l[3]));
}

// 4 weight matrices in one launch (blockIdx.y selects)
__global__ void wsplit_kernel(const float* __restrict__ Wq, const float* __restrict__ Wk,
                              const float* __restrict__ Wv, const float* __restrict__ Wp,
                              __nv_bfloat16* __restrict__ qh, __nv_bfloat16* __restrict__ ql,
                              __nv_bfloat16* __restrict__ kh, __nv_bfloat16* __restrict__ kl,
                              __nv_bfloat16* __restrict__ vh, __nv_bfloat16* __restrict__ vl,
                              __nv_bfloat16* __restrict__ ph, __nv_bfloat16* __restrict__ pl,
                              int n4)
{
    const int i = blockIdx.x * blockDim.x + threadIdx.x;
    if (i >= n4) return;
    const int m = blockIdx.y;
    const float* in = (m == 0) ? Wq : (m == 1) ? Wk : (m == 2) ? Wv : Wp;
    __nv_bfloat16* hi = (m == 0) ? qh : (m == 1) ? kh : (m == 2) ? vh : ph;
    __nv_bfloat16* lo = (m == 0) ? ql : (m == 1) ? kl : (m == 2) ? vl : pl;
    const float4 v = reinterpret_cast<const float4*>(in)[i];
    float f[4] = {v.x, v.y, v.z, v.w};
    float l[4];
    #pragma unroll
    for (int j = 0; j < 4; j++) {
        const __nv_bfloat16 h = __float2bfloat16(f[j]);
        l[j] = f[j] - __bfloat162float(h);
    }
    reinterpret_cast<uint2*>(hi)[i] =
        make_uint2(pack_bf2(f[0], f[1]), pack_bf2(f[2], f[3]));
    reinterpret_cast<uint2*>(lo)[i] =
        make_uint2(pack_bf2(l[0], l[1]), pack_bf2(l[2], l[3]));
}

// ---------------------------------------------------------------------------
// Row softmax over S=2048, emitting bf16 hi/lo of the result.
// ---------------------------------------------------------------------------
__global__ __launch_bounds__(256) void softmax_split(const float* __restrict__ P,
                                                     __nv_bfloat16* __restrict__ Phi,
                                                     __nv_bfloat16* __restrict__ Plo)
{
    const size_t rowoff = (size_t)blockIdx.x * SS;
    const float* row = P + rowoff;
    const int tid = threadIdx.x;
    __shared__ float red[8];

    float4 v0 = __ldcs(((const float4*)row) + tid);
    float4 v1 = __ldcs(((const float4*)row) + tid + 256);

    float m = fmaxf(fmaxf(fmaxf(v0.x, v0.y), fmaxf(v0.z, v0.w)),
                    fmaxf(fmaxf(v1.x, v1.y), fmaxf(v1.z, v1.w)));
    #pragma unroll
    for (int o = 16; o > 0; o >>= 1)
        m = fmaxf(m, __shfl_xor_sync(0xffffffffu, m, o));
    if ((tid & 31) == 0) red[tid >> 5] = m;
    __syncthreads();
    float bmax = red[0];
    #pragma unroll
    for (int i = 1; i < 8; i++) bmax = fmaxf(bmax, red[i]);
    __syncthreads();

    v0.x = __expf(v0.x - bmax); v0.y = __expf(v0.y - bmax);
    v0.z = __expf(v0.z - bmax); v0.w = __expf(v0.w - bmax);
    v1.x = __expf(v1.x - bmax); v1.y = __expf(v1.y - bmax);
    v1.z = __expf(v1.z - bmax); v1.w = __expf(v1.w - bmax);

    float s = v0.x + v0.y + v0.z + v0.w + v1.x + v1.y + v1.z + v1.w;
    #pragma unroll
    for (int o = 16; o > 0; o >>= 1)
        s += __shfl_xor_sync(0xffffffffu, s, o);
    if ((tid & 31) == 0) red[tid >> 5] = s;
    __syncthreads();
    float total = 0.0f;
    #pragma unroll
    for (int i = 0; i < 8; i++) total += red[i];
    const float inv = __frcp_rn(total);

    float f[8] = {v0.x * inv, v0.y * inv, v0.z * inv, v0.w * inv,
                  v1.x * inv, v1.y * inv, v1.z * inv, v1.w * inv};
    float l[8];
    #pragma unroll
    for (int j = 0; j < 8; j++) {
        const __nv_bfloat16 h = __float2bfloat16(f[j]);
        l[j] = f[j] - __bfloat162float(h);
    }
    uint2* ph = reinterpret_cast<uint2*>(Phi + rowoff);
    uint2* pl = reinterpret_cast<uint2*>(Plo + rowoff);
    ph[tid]       = make_uint2(pack_bf2(f[0], f[1]), pack_bf2(f[2], f[3]));
    ph[tid + 256] = make_uint2(pack_bf2(f[4], f[5]), pack_bf2(f[6], f[7]));
    pl[tid]       = make_uint2(pack_bf2(l[0], l[1]), pack_bf2(l[2], l[3]));
    pl[tid + 256] = make_uint2(pack_bf2(l[4], l[5]), pack_bf2(l[6], l[7]));
}

// ---------------------------------------------------------------------------
extern "C" void kernel_launch(void* const* d_in, const int* in_sizes, int n_in,
                              void* d_out, int out_size)
{
    const float* x  = (const float*)d_in[0];
    const float* Wq = (const float*)d_in[1];
    const float* bq = (const float*)d_in[2];
    const float* Wk = (const float*)d_in[3];
    const float* bk = (const float*)d_in[4];
    const float* Wv = (const float*)d_in[5];
    const float* bv = (const float*)d_in[6];
    const float* Wp = (const float*)d_in[7];
    const float* bp = (const float*)d_in[8];
    float* out = (float*)d_out;

    __nv_bfloat16 *xhi, *xlo, *Wqhi, *Wqlo, *Wkhi, *Wklo, *Wvhi, *Wvlo, *Wphi, *Wplo;
    __nv_bfloat16 *Qhi, *Qlo, *Khi, *Klo, *Vthi, *Vtlo, *Phi, *Plo, *Ohi, *Olo;
    float *P;
    cudaGetSymbolAddress((void**)&xhi, g_xhi);   cudaGetSymbolAddress((void**)&xlo, g_xlo);
    cudaGetSymbolAddress((void**)&Wqhi, g_Wqhi); cudaGetSymbolAddress((void**)&Wqlo, g_Wqlo);
    cudaGetSymbolAddress((void**)&Wkhi, g_Wkhi); cudaGetSymbolAddress((void**)&Wklo, g_Wklo);
    cudaGetSymbolAddress((void**)&Wvhi, g_Wvhi); cudaGetSymbolAddress((void**)&Wvlo, g_Wvlo);
    cudaGetSymbolAddress((void**)&Wphi, g_Wphi); cudaGetSymbolAddress((void**)&Wplo, g_Wplo);
    cudaGetSymbolAddress((void**)&Qhi, g_Qhi);   cudaGetSymbolAddress((void**)&Qlo, g_Qlo);
    cudaGetSymbolAddress((void**)&Khi, g_Khi);   cudaGetSymbolAddress((void**)&Klo, g_Klo);
    cudaGetSymbolAddress((void**)&Vthi, g_Vthi); cudaGetSymbolAddress((void**)&Vtlo, g_Vtlo);
    cudaGetSymbolAddress((void**)&P, g_P);
    cudaGetSymbolAddress((void**)&Phi, g_Phi);   cudaGetSymbolAddress((void**)&Plo, g_Plo);
    cudaGetSymbolAddress((void**)&Ohi, g_Ohi);   cudaGetSymbolAddress((void**)&Olo, g_Olo);

    cudaFuncSetAttribute(mma_gemm, cudaFuncAttributeMaxDynamicSharedMemorySize,
                         GEMM_SMEM_BYTES);
    cudaFuncSetAttribute(proj_qkv, cudaFuncAttributeMaxDynamicSharedMemorySize,
                         GEMM_SMEM_BYTES);

    const float alpha = 1.0f / sqrtf((float)DD);
    const size_t sQK = (size_t)SS * DD;
    const size_t sP  = (size_t)SS * SS;

    // splits
    {
        const int n4x = BB * SS * DD / 4;
        split_kernel<<<(n4x + 255) / 256, 256>>>(x, xhi, xlo, n4x);
        const int n4w = DD * DD / 4;
        wsplit_kernel<<<dim3((n4w + 255) / 256, 4), 256>>>(
            Wq, Wk, Wv, Wp, Wqhi, Wqlo, Wkhi, Wklo, Wvhi, Wvlo, Wphi, Wplo, n4w);
    }

    const dim3 blk(256);

    // fused Q/K/V projections (V emitted transposed)
    proj_qkv<<<dim3(DD / 128, (BB * SS) / 128, 3), blk, GEMM_SMEM_BYTES>>>(
        xhi, xlo, Wqhi, Wqlo, Wkhi, Wklo, Wvhi, Wvlo, bq, bk, bv,
        Qhi, Qlo, Khi, Klo, Vthi, Vtlo);

    // P = (Q@K^T)/sqrt(D) (fp32)
    mma_gemm<<<dim3(SS / 128, SS / 128, BB), blk, GEMM_SMEM_BYTES>>>(
        Qhi, Qlo, Khi, Klo, nullptr, alpha, P, nullptr, nullptr,
        SS, DD, sQK, sQK, sP);

    // softmax rows -> bf16 hi/lo
    softmax_split<<<BB * SS, 256>>>(P, Phi, Plo);

    // O = P@V (NT against Vt[D,S]; emit bf16 hi/lo)
    mma_gemm<<<dim3(DD / 128, SS / 128, BB), blk, GEMM_SMEM_BYTES>>>(
        Phi, Plo, Vthi, Vtlo, nullptr, 1.0f, nullptr, Ohi, Olo,
        DD, SS, sP, (size_t)DD * SS, sQK);

    // out = O@Wp^T + bp (fp32)
    mma_gemm<<<dim3(DD / 128, (BB * SS) / 128, 1), blk, GEMM_SMEM_BYTES>>>(
        Ohi, Olo, Wphi, Wplo, bp, 1.0f, out, nullptr, nullptr, DD, DD, 0, 0, 0);
}

// round 11
// speedup vs baseline: 2.1097x; 1.0360x over previous
#include <cuda_runtime.h>
#include <cuda_bf16.h>
#include <math.h>
#include <stdint.h>

#define BB 8
#define SS 2048
#define DD 768

// ---------------------------------------------------------------------------
// Scratch (device globals: allocation-free per harness rules)
// ---------------------------------------------------------------------------
__device__ __nv_bfloat16 g_xhi[BB * SS * DD], g_xlo[BB * SS * DD];
__device__ __nv_bfloat16 g_Wqhi[DD * DD], g_Wqlo[DD * DD];
__device__ __nv_bfloat16 g_Wkhi[DD * DD], g_Wklo[DD * DD];
__device__ __nv_bfloat16 g_Wvhi[DD * DD], g_Wvlo[DD * DD];
__device__ __nv_bfloat16 g_Wphi[DD * DD], g_Wplo[DD * DD];
__device__ __nv_bfloat16 g_Qhi[BB * SS * DD], g_Qlo[BB * SS * DD];
__device__ __nv_bfloat16 g_Khi[BB * SS * DD], g_Klo[BB * SS * DD];
__device__ __nv_bfloat16 g_Vthi[BB * DD * SS], g_Vtlo[BB * DD * SS];
__device__ float         g_P[(size_t)BB * SS * SS];
__device__ __nv_bfloat16 g_Phi[(size_t)BB * SS * SS], g_Plo[(size_t)BB * SS * SS];
__device__ __nv_bfloat16 g_Ohi[BB * SS * DD], g_Olo[BB * SS * DD];

// ---------------------------------------------------------------------------
// Portable PTX helpers (no 'a'-gated features: ldmatrix / mma.sync / cp.async)
// ---------------------------------------------------------------------------
__device__ __forceinline__ uint32_t smem_to_u32(const void* p) {
    uint32_t a;
    asm("{ .reg .u64 t; cvta.to.shared.u64 t, %1; cvt.u32.u64 %0, t; }"
        : "=r"(a) : "l"(p));
    return a;
}

#define CP_ASYNC16(saddr, gaddr) \
    asm volatile("cp.async.cg.shared.global [%0], [%1], 16;" :: "r"(saddr), "l"(gaddr))
#define CP_COMMIT() asm volatile("cp.async.commit_group;" ::: "memory")
#define CP_WAIT(N)  asm volatile("cp.async.wait_group %0;" :: "n"(N) : "memory")

__device__ __forceinline__ void ldm_x4(uint32_t* r, uint32_t addr) {
    asm volatile("ldmatrix.sync.aligned.m8n8.x4.shared.b16 {%0,%1,%2,%3}, [%4];"
                 : "=r"(r[0]), "=r"(r[1]), "=r"(r[2]), "=r"(r[3]) : "r"(addr));
}

__device__ __forceinline__ void mma_bf16(float* c, const uint32_t* a,
                                         uint32_t b0, uint32_t b1) {
    asm volatile(
        "mma.sync.aligned.m16n8k16.row.col.f32.bf16.bf16.f32 "
        "{%0,%1,%2,%3}, {%4,%5,%6,%7}, {%8,%9}, {%0,%1,%2,%3};"
        : "+f"(c[0]), "+f"(c[1]), "+f"(c[2]), "+f"(c[3])
        : "r"(a[0]), "r"(a[1]), "r"(a[2]), "r"(a[3]), "r"(b0), "r"(b1));
}

__device__ __forceinline__ uint32_t pack_bf2(float a, float b) {
    __nv_bfloat162 t(__float2bfloat16(a), __float2bfloat16(b));
    return *reinterpret_cast<uint32_t*>(&t);
}

// ---------------------------------------------------------------------------
// Shared GEMM-tile machinery (256 thr, 8 warps, warp 32x64, 128x128 block
// tile, BK=32, double-buffered cp.async, 2 CTAs/SM, ONE sync per chunk)
// ---------------------------------------------------------------------------
#define ROWB 80                      // smem row pitch bytes (64B data + 16B pad)
#define MATB (128 * ROWB)            // 10240 B per matrix tile
#define STGB (4 * MATB)              // 40960 B per stage (Ah,Al,Bh,Bl)
#define GEMM_SMEM_BYTES (2 * STGB)   // 81920

// Runs the full K-loop. NOTE: no trailing __syncthreads after the last chunk;
// callers that reuse smem afterwards must sync first.
__device__ __forceinline__ void gemm_mainloop(
    uint32_t sb, int tid,
    const __nv_bfloat16* Ahi, const __nv_bfloat16* Alo,
    const __nv_bfloat16* Bhi, const __nv_bfloat16* Blo,
    int bm, int bn, int K, float (*acc)[8][4])
{
    const int wid = tid >> 5;
    const int lid = tid & 31;
    const int wm = (wid & 3) << 5;
    const int wn = (wid >> 2) << 6;

    const int grow = tid >> 1;
    const int ghalf = (tid & 1) << 4;
    const uint32_t soff = grow * ROWB + ((tid & 1) << 5);

    auto issue_stage = [&](int c, int stg) {
        const int k0 = c << 5;
        const uint32_t s0 = sb + stg * STGB + soff;
        const __nv_bfloat16* gA  = Ahi + (size_t)(bm + grow) * K + k0 + ghalf;
        const __nv_bfloat16* gAl = Alo + (size_t)(bm + grow) * K + k0 + ghalf;
        const __nv_bfloat16* gB  = Bhi + (size_t)(bn + grow) * K + k0 + ghalf;
        const __nv_bfloat16* gBl = Blo + (size_t)(bn + grow) * K + k0 + ghalf;
        CP_ASYNC16(s0 + 0 * MATB,      gA);
        CP_ASYNC16(s0 + 0 * MATB + 16, gA + 8);
        CP_ASYNC16(s0 + 1 * MATB,      gAl);
        CP_ASYNC16(s0 + 1 * MATB + 16, gAl + 8);
        CP_ASYNC16(s0 + 2 * MATB,      gB);
        CP_ASYNC16(s0 + 2 * MATB + 16, gB + 8);
        CP_ASYNC16(s0 + 3 * MATB,      gBl);
        CP_ASYNC16(s0 + 3 * MATB + 16, gBl + 8);
    };

    const uint32_t aLane = (uint32_t)(wm + (lid & 15)) * ROWB + ((lid >> 4) << 4);
    const uint32_t bLane = (uint32_t)(wn + (lid & 7) + ((lid >> 4) << 3)) * ROWB
                           + (((lid >> 3) & 1) << 4);

    const int nch = K >> 5;
    issue_stage(0, 0);
    CP_COMMIT();

    for (int c = 0; c < nch; c++) {
        // stage c is the only outstanding group -> wait for it
        CP_WAIT(0);
        // one barrier: (a) data of stage c visible to all warps,
        // (b) all warps finished reading slot (c-1)&1 in the previous chunk,
        //     so it is safe to overwrite it with stage c+1 below.
        __syncthreads();
        if (c + 1 < nch) {
            issue_stage(c + 1, (c + 1) & 1);
            CP_COMMIT();
        }

        const uint32_t stg = sb + (c & 1) * STGB;
        #pragma unroll
        for (int ks = 0; ks < 2; ks++) {
            const uint32_t kb = ks << 5;
            uint32_t aH[2][4], aL[2][4], bF[4][4];
            #pragma unroll
            for (int mt = 0; mt < 2; mt++)
                ldm_x4(aH[mt], stg + 0 * MATB + aLane + mt * (16 * ROWB) + kb);
            #pragma unroll
            for (int mt = 0; mt < 2; mt++)
                ldm_x4(aL[mt], stg + 1 * MATB + aLane + mt * (16 * ROWB) + kb);
            #pragma unroll
            for (int g = 0; g < 4; g++)
                ldm_x4(bF[g], stg + 2 * MATB + bLane + g * (16 * ROWB) + kb);
            // hh
            #pragma unroll
            for (int mt = 0; mt < 2; mt++)
                #pragma unroll
                for (int g = 0; g < 4; g++) {
                    mma_bf16(acc[mt][2 * g],     aH[mt], bF[g][0], bF[g][1]);
                    mma_bf16(acc[mt][2 * g + 1], aH[mt], bF[g][2], bF[g][3]);
                }
            // lh (B-hi resident)
            #pragma unroll
            for (int mt = 0; mt < 2; mt++)
                #pragma unroll
                for (int g = 0; g < 4; g++) {
                    mma_bf16(acc[mt][2 * g],     aL[mt], bF[g][0], bF[g][1]);
                    mma_bf16(acc[mt][2 * g + 1], aL[mt], bF[g][2], bF[g][3]);
                }
            // hl
            #pragma unroll
            for (int g = 0; g < 4; g++)
                ldm_x4(bF[g], stg + 3 * MATB + bLane + g * (16 * ROWB) + kb);
            #pragma unroll
            for (int mt = 0; mt < 2; mt++)
                #pragma unroll
                for (int g = 0; g < 4; g++) {
                    mma_bf16(acc[mt][2 * g],     aH[mt], bF[g][0], bF[g][1]);
                    mma_bf16(acc[mt][2 * g + 1], aH[mt], bF[g][2], bF[g][3]);
                }
        }
        // no trailing sync: next iteration's barrier covers buffer reuse
    }
}

// ---------------------------------------------------------------------------
// Generic split-bf16 GEMM (NT): used for QK^T, P@Vt, out-projection.
// ---------------------------------------------------------------------------
__global__ __launch_bounds__(256, 2) void mma_gemm(
    const __nv_bfloat16* __restrict__ Ahi, const __nv_bfloat16* __restrict__ Alo,
    const __nv_bfloat16* __restrict__ Bhi, const __nv_bfloat16* __restrict__ Blo,
    const float* __restrict__ bias, float alpha,
    float* __restrict__ Cf,
    __nv_bfloat16* __restrict__ Chi, __nv_bfloat16* __restrict__ Clo,
    int ldc, int K, size_t strA, size_t strB, size_t strC)
{
    extern __shared__ char smem[];
    const uint32_t sb = smem_to_u32(smem);
    const int tid = threadIdx.x;
    const int wid = tid >> 5;
    const int lid = tid & 31;
    const int bm = blockIdx.y << 7;
    const int bn = blockIdx.x << 7;
    const int wm = (wid & 3) << 5;
    const int wn = (wid >> 2) << 6;

    float acc[2][8][4];
    #pragma unroll
    for (int i = 0; i < 2; i++)
        #pragma unroll
        for (int j = 0; j < 8; j++)
            #pragma unroll
            for (int q = 0; q < 4; q++) acc[i][j][q] = 0.0f;

    gemm_mainloop(sb, tid, Ahi + blockIdx.z * strA, Alo + blockIdx.z * strA,
                  Bhi + blockIdx.z * strB, Blo + blockIdx.z * strB,
                  bm, bn, K, acc);

    const int r0 = lid >> 2;
    const int cq = (lid & 3) << 1;
    #pragma unroll
    for (int mt = 0; mt < 2; mt++) {
        #pragma unroll
        for (int half = 0; half < 2; half++) {
            const int row = bm + wm + mt * 16 + r0 + half * 8;
            const size_t base = blockIdx.z * strC + (size_t)row * ldc + bn + wn;
            #pragma unroll
            for (int nt = 0; nt < 8; nt++) {
                const int col = wn + nt * 8 + cq;
                float v0 = acc[mt][nt][half * 2]     * alpha;
                float v1 = acc[mt][nt][half * 2 + 1] * alpha;
                if (bias) {
                    v0 += __ldg(bias + bn + col);
                    v1 += __ldg(bias + bn + col + 1);
                }
                if (Cf)
                    __stcs(reinterpret_cast<float2*>(Cf + base + nt * 8 + cq),
                           make_float2(v0, v1));
                if (Chi) {
                    const __nv_bfloat16 h0 = __float2bfloat16(v0);
                    const __nv_bfloat16 h1 = __float2bfloat16(v1);
                    const float l0 = v0 - __bfloat162float(h0);
                    const float l1 = v1 - __bfloat162float(h1);
                    __nv_bfloat162 hp(h0, h1);
                    __nv_bfloat162 lp(__float2bfloat16(l0), __float2bfloat16(l1));
                    *reinterpret_cast<uint32_t*>(Chi + base + nt * 8 + cq) =
                        *reinterpret_cast<uint32_t*>(&hp);
                    *reinterpret_cast<uint32_t*>(Clo + base + nt * 8 + cq) =
                        *reinterpret_cast<uint32_t*>(&lp);
                }
            }
        }
    }
}

// ---------------------------------------------------------------------------
// Fused QKV projection: z=0 -> Q(hi/lo), z=1 -> K(hi/lo),
// z=2 -> V emitted TRANSPOSED as Vt[b][d][s] hi/lo (via smem transpose).
// grid = (DD/128, BB*SS/128, 3)
// ---------------------------------------------------------------------------
__global__ __launch_bounds__(256, 2) void proj_qkv(
    const __nv_bfloat16* __restrict__ xhi, const __nv_bfloat16* __restrict__ xlo,
    const __nv_bfloat16* __restrict__ Wqh, const __nv_bfloat16* __restrict__ Wql,
    const __nv_bfloat16* __restrict__ Wkh, const __nv_bfloat16* __restrict__ Wkl,
    const __nv_bfloat16* __restrict__ Wvh, const __nv_bfloat16* __restrict__ Wvl,
    const float* __restrict__ bq, const float* __restrict__ bk,
    const float* __restrict__ bv,
    __nv_bfloat16* __restrict__ Qhi, __nv_bfloat16* __restrict__ Qlo,
    __nv_bfloat16* __restrict__ Khi, __nv_bfloat16* __restrict__ Klo,
    __nv_bfloat16* __restrict__ Vthi, __nv_bfloat16* __restrict__ Vtlo)
{
    extern __shared__ char smem[];
    const uint32_t sb = smem_to_u32(smem);
    const int tid = threadIdx.x;
    const int wid = tid >> 5;
    const int lid = tid & 31;
    const int bm = blockIdx.y << 7;
    const int bn = blockIdx.x << 7;
    const int wm = (wid & 3) << 5;
    const int wn = (wid >> 2) << 6;
    const int z = blockIdx.z;

    const __nv_bfloat16* Bh = (z == 0) ? Wqh : (z == 1) ? Wkh : Wvh;
    const __nv_bfloat16* Bl = (z == 0) ? Wql : (z == 1) ? Wkl : Wvl;
    const float* bias       = (z == 0) ? bq  : (z == 1) ? bk  : bv;

    float acc[2][8][4];
    #pragma unroll
    for (int i = 0; i < 2; i++)
        #pragma unroll
        for (int j = 0; j < 8; j++)
            #pragma unroll
            for (int q = 0; q < 4; q++) acc[i][j][q] = 0.0f;

    gemm_mainloop(sb, tid, xhi, xlo, Bh, Bl, bm, bn, DD, acc);

    const int r0 = lid >> 2;
    const int cq = (lid & 3) << 1;

    if (z < 2) {
        __nv_bfloat16* Chi = (z == 0) ? Qhi : Khi;
        __nv_bfloat16* Clo = (z == 0) ? Qlo : Klo;
        #pragma unroll
        for (int mt = 0; mt < 2; mt++) {
            #pragma unroll
            for (int half = 0; half < 2; half++) {
                const int row = bm + wm + mt * 16 + r0 + half * 8;
                const size_t base = (size_t)row * DD + bn + wn;
                #pragma unroll
                for (int nt = 0; nt < 8; nt++) {
                    const int col = wn + nt * 8 + cq;
                    float v0 = acc[mt][nt][half * 2]     + __ldg(bias + bn + col);
                    float v1 = acc[mt][nt][half * 2 + 1] + __ldg(bias + bn + col + 1);
                    const __nv_bfloat16 h0 = __float2bfloat16(v0);
                    const __nv_bfloat16 h1 = __float2bfloat16(v1);
                    const float l0 = v0 - __bfloat162float(h0);
                    const float l1 = v1 - __bfloat162float(h1);
                    __nv_bfloat162 hp(h0, h1);
                    __nv_bfloat162 lp(__float2bfloat16(l0), __float2bfloat16(l1));
                    *reinterpret_cast<uint32_t*>(Chi + base + nt * 8 + cq) =
                        *reinterpret_cast<uint32_t*>(&hp);
                    *reinterpret_cast<uint32_t*>(Clo + base + nt * 8 + cq) =
                        *reinterpret_cast<uint32_t*>(&lp);
                }
            }
        }
    } else {
        // Mainloop no longer ends with a barrier; smem stage buffers may still
        // be read by other warps. Sync before reusing smem for the transpose.
        __syncthreads();
        // V: write transposed tile via smem. sfT[col][row] (pitch 130 floats).
        float* sf = reinterpret_cast<float*>(smem);
        #pragma unroll
        for (int mt = 0; mt < 2; mt++) {
            #pragma unroll
            for (int half = 0; half < 2; half++) {
                const int rloc = wm + mt * 16 + r0 + half * 8;
                #pragma unroll
                for (int nt = 0; nt < 8; nt++) {
                    const int col = wn + nt * 8 + cq;
                    float v0 = acc[mt][nt][half * 2]     + __ldg(bias + bn + col);
                    float v1 = acc[mt][nt][half * 2 + 1] + __ldg(bias + bn + col + 1);
                    sf[(size_t)col * 130 + rloc]       = v0;
                    sf[(size_t)(col + 1) * 130 + rloc] = v1;
                }
            }
        }
        __syncthreads();
        // write Vt[b][bn+d][s_base + sc .. +63], hi/lo split on the fly
        const int b = bm >> 11;           // 2048 rows per batch; 128 | 2048
        const int s_base = bm & (SS - 1);
        const int d = tid >> 1;           // 0..127
        const int sc = (tid & 1) << 6;    // 0 / 64
        const float* srow = sf + (size_t)d * 130 + sc;
        __nv_bfloat16* th = Vthi + ((size_t)b * DD + bn + d) * SS + s_base + sc;
        __nv_bfloat16* tl = Vtlo + ((size_t)b * DD + bn + d) * SS + s_base + sc;
        #pragma unroll
        for (int j = 0; j < 64; j += 8) {
            uint4 ph, pl;
            uint32_t* php = reinterpret_cast<uint32_t*>(&ph);
            uint32_t* plp = reinterpret_cast<uint32_t*>(&pl);
            #pragma unroll
            for (int p = 0; p < 4; p++) {
                const float a = srow[j + 2 * p], c = srow[j + 2 * p + 1];
                const __nv_bfloat16 ha = __float2bfloat16(a);
                const __nv_bfloat16 hc = __float2bfloat16(c);
                __nv_bfloat162 hp2(ha, hc);
                __nv_bfloat162 lp2(__float2bfloat16(a - __bfloat162float(ha)),
                                   __float2bfloat16(c - __bfloat162float(hc)));
                php[p] = *reinterpret_cast<uint32_t*>(&hp2);
                plp[p] = *reinterpret_cast<uint32_t*>(&lp2);
            }
            *reinterpret_cast<uint4*>(th + j) = ph;
            *reinterpret_cast<uint4*>(tl + j) = pl;
        }
    }
}

// ---------------------------------------------------------------------------
// fp32 -> bf16 hi/lo split (vectorized)
// ---------------------------------------------------------------------------
__global__ void split_kernel(const float* __restrict__ in,
                             __nv_bfloat16* __restrict__ hi,
                             __nv_bfloat16* __restrict__ lo, int n4)
{
    const int i = blockIdx.x * blockDim.x + threadIdx.x;
    if (i >= n4) return;
    const float4 v = reinterpret_cast<const float4*>(in)[i];
    float f[4] = {v.x, v.y, v.z, v.w};
    float l[4];
    #pragma unroll
    for (int j = 0; j < 4; j++) {
        const __nv_bfloat16 h = __float2bfloat16(f[j]);
        l[j] = f[j] - __bfloat162float(h);
    }
    reinterpret_cast<uint2*>(hi)[i] =
        make_uint2(pack_bf2(f[0], f[1]), pack_bf2(f[2], f[3]));
    reinterpret_cast<uint2*>(lo)[i] =
        make_uint2(pack_bf2(l[0], l[1]), pack_bf2(l[2], l[3]));
}

// 4 weight matrices in one launch (blockIdx.y selects)
__global__ void wsplit_kernel(const float* __restrict__ Wq, const float* __restrict__ Wk,
                              const float* __restrict__ Wv, const float* __restrict__ Wp,
                              __nv_bfloat16* __restrict__ qh, __nv_bfloat16* __restrict__ ql,
                              __nv_bfloat16* __restrict__ kh, __nv_bfloat16* __restrict__ kl,
                              __nv_bfloat16* __restrict__ vh, __nv_bfloat16* __restrict__ vl,
                              __nv_bfloat16* __restrict__ ph, __nv_bfloat16* __restrict__ pl,
                              int n4)
{
    const int i = blockIdx.x * blockDim.x + threadIdx.x;
    if (i >= n4) return;
    const int m = blockIdx.y;
    const float* in = (m == 0) ? Wq : (m == 1) ? Wk : (m == 2) ? Wv : Wp;
    __nv_bfloat16* hi = (m == 0) ? qh : (m == 1) ? kh : (m == 2) ? vh : ph;
    __nv_bfloat16* lo = (m == 0) ? ql : (m == 1) ? kl : (m == 2) ? vl : pl;
    const float4 v = reinterpret_cast<const float4*>(in)[i];
    float f[4] = {v.x, v.y, v.z, v.w};
    float l[4];
    #pragma unroll
    for (int j = 0; j < 4; j++) {
        const __nv_bfloat16 h = __float2bfloat16(f[j]);
        l[j] = f[j] - __bfloat162float(h);
    }
    reinterpret_cast<uint2*>(hi)[i] =
        make_uint2(pack_bf2(f[0], f[1]), pack_bf2(f[2], f[3]));
    reinterpret_cast<uint2*>(lo)[i] =
        make_uint2(pack_bf2(l[0], l[1]), pack_bf2(l[2], l[3]));
}

// ---------------------------------------------------------------------------
// Row softmax over S=2048, emitting bf16 hi/lo of the result.
// ---------------------------------------------------------------------------
__global__ __launch_bounds__(256) void softmax_split(const float* __restrict__ P,
                                                     __nv_bfloat16* __restrict__ Phi,
                                                     __nv_bfloat16* __restrict__ Plo)
{
    const size_t rowoff = (size_t)blockIdx.x * SS;
    const float* row = P + rowoff;
    const int tid = threadIdx.x;
    __shared__ float red[8];

    float4 v0 = __ldcs(((const float4*)row) + tid);
    float4 v1 = __ldcs(((const float4*)row) + tid + 256);

    float m = fmaxf(fmaxf(fmaxf(v0.x, v0.y), fmaxf(v0.z, v0.w)),
                    fmaxf(fmaxf(v1.x, v1.y), fmaxf(v1.z, v1.w)));
    #pragma unroll
    for (int o = 16; o > 0; o >>= 1)
        m = fmaxf(m, __shfl_xor_sync(0xffffffffu, m, o));
    if ((tid & 31) == 0) red[tid >> 5] = m;
    __syncthreads();
    float bmax = red[0];
    #pragma unroll
    for (int i = 1; i < 8; i++) bmax = fmaxf(bmax, red[i]);
    __syncthreads();

    v0.x = __expf(v0.x - bmax); v0.y = __expf(v0.y - bmax);
    v0.z = __expf(v0.z - bmax); v0.w = __expf(v0.w - bmax);
    v1.x = __expf(v1.x - bmax); v1.y = __expf(v1.y - bmax);
    v1.z = __expf(v1.z - bmax); v1.w = __expf(v1.w - bmax);

    float s = v0.x + v0.y + v0.z + v0.w + v1.x + v1.y + v1.z + v1.w;
    #pragma unroll
    for (int o = 16; o > 0; o >>= 1)
        s += __shfl_xor_sync(0xffffffffu, s, o);
    if ((tid & 31) == 0) red[tid >> 5] = s;
    __syncthreads();
    float total = 0.0f;
    #pragma unroll
    for (int i = 0; i < 8; i++) total += red[i];
    const float inv = __frcp_rn(total);

    float f[8] = {v0.x * inv, v0.y * inv, v0.z * inv, v0.w * inv,
                  v1.x * inv, v1.y * inv, v1.z * inv, v1.w * inv};
    float l[8];
    #pragma unroll
    for (int j = 0; j < 8; j++) {
        const __nv_bfloat16 h = __float2bfloat16(f[j]);
        l[j] = f[j] - __bfloat162float(h);
    }
    uint2* ph = reinterpret_cast<uint2*>(Phi + rowoff);
    uint2* pl = reinterpret_cast<uint2*>(Plo + rowoff);
    ph[tid]       = make_uint2(pack_bf2(f[0], f[1]), pack_bf2(f[2], f[3]));
    ph[tid + 256] = make_uint2(pack_bf2(f[4], f[5]), pack_bf2(f[6], f[7]));
    pl[tid]       = make_uint2(pack_bf2(l[0], l[1]), pack_bf2(l[2], l[3]));
    pl[tid + 256] = make_uint2(pack_bf2(l[4], l[5]), pack_bf2(l[6], l[7]));
}

// ---------------------------------------------------------------------------
extern "C" void kernel_launch(void* const* d_in, const int* in_sizes, int n_in,
                              void* d_out, int out_size)
{
    const float* x  = (const float*)d_in[0];
    const float* Wq = (const float*)d_in[1];
    const float* bq = (const float*)d_in[2];
    const float* Wk = (const float*)d_in[3];
    const float* bk = (const float*)d_in[4];
    const float* Wv = (const float*)d_in[5];
    const float* bv = (const float*)d_in[6];
    const float* Wp = (const float*)d_in[7];
    const float* bp = (const float*)d_in[8];
    float* out = (float*)d_out;

    __nv_bfloat16 *xhi, *xlo, *Wqhi, *Wqlo, *Wkhi, *Wklo, *Wvhi, *Wvlo, *Wphi, *Wplo;
    __nv_bfloat16 *Qhi, *Qlo, *Khi, *Klo, *Vthi, *Vtlo, *Phi, *Plo, *Ohi, *Olo;
    float *P;
    cudaGetSymbolAddress((void**)&xhi, g_xhi);   cudaGetSymbolAddress((void**)&xlo, g_xlo);
    cudaGetSymbolAddress((void**)&Wqhi, g_Wqhi); cudaGetSymbolAddress((void**)&Wqlo, g_Wqlo);
    cudaGetSymbolAddress((void**)&Wkhi, g_Wkhi); cudaGetSymbolAddress((void**)&Wklo, g_Wklo);
    cudaGetSymbolAddress((void**)&Wvhi, g_Wvhi); cudaGetSymbolAddress((void**)&Wvlo, g_Wvlo);
    cudaGetSymbolAddress((void**)&Wphi, g_Wphi); cudaGetSymbolAddress((void**)&Wplo, g_Wplo);
    cudaGetSymbolAddress((void**)&Qhi, g_Qhi);   cudaGetSymbolAddress((void**)&Qlo, g_Qlo);
    cudaGetSymbolAddress((void**)&Khi, g_Khi);   cudaGetSymbolAddress((void**)&Klo, g_Klo);
    cudaGetSymbolAddress((void**)&Vthi, g_Vthi); cudaGetSymbolAddress((void**)&Vtlo, g_Vtlo);
    cudaGetSymbolAddress((void**)&P, g_P);
    cudaGetSymbolAddress((void**)&Phi, g_Phi);   cudaGetSymbolAddress((void**)&Plo, g_Plo);
    cudaGetSymbolAddress((void**)&Ohi, g_Ohi);   cudaGetSymbolAddress((void**)&Olo, g_Olo);

    cudaFuncSetAttribute(mma_gemm, cudaFuncAttributeMaxDynamicSharedMemorySize,
                         GEMM_SMEM_BYTES);
    cudaFuncSetAttribute(proj_qkv, cudaFuncAttributeMaxDynamicSharedMemorySize,
                         GEMM_SMEM_BYTES);

    const float alpha = 1.0f / sqrtf((float)DD);
    const size_t sQK = (size_t)SS * DD;
    const size_t sP  = (size_t)SS * SS;

    // splits
    {
        const int n4x = BB * SS * DD / 4;
        split_kernel<<<(n4x + 255) / 256, 256>>>(x, xhi, xlo, n4x);
        const int n4w = DD * DD / 4;
        wsplit_kernel<<<dim3((n4w + 255) / 256, 4), 256>>>(
            Wq, Wk, Wv, Wp, Wqhi, Wqlo, Wkhi, Wklo, Wvhi, Wvlo, Wphi, Wplo, n4w);
    }

    const dim3 blk(256);

    // fused Q/K/V projections (V emitted transposed)
    proj_qkv<<<dim3(DD / 128, (BB * SS) / 128, 3), blk, GEMM_SMEM_BYTES>>>(
        xhi, xlo, Wqhi, Wqlo, Wkhi, Wklo, Wvhi, Wvlo, bq, bk, bv,
        Qhi, Qlo, Khi, Klo, Vthi, Vtlo);

    // P = (Q@K^T)/sqrt(D) (fp32)
    mma_gemm<<<dim3(SS / 128, SS / 128, BB), blk, GEMM_SMEM_BYTES>>>(
        Qhi, Qlo, Khi, Klo, nullptr, alpha, P, nullptr, nullptr,
        SS, DD, sQK, sQK, sP);

    // softmax rows -> bf16 hi/lo
    softmax_split<<<BB * SS, 256>>>(P, Phi, Plo);

    // O = P@V (NT against Vt[D,S]; emit bf16 hi/lo)
    mma_gemm<<<dim3(DD / 128, SS / 128, BB), blk, GEMM_SMEM_BYTES>>>(
        Phi, Plo, Vthi, Vtlo, nullptr, 1.0f, nullptr, Ohi, Olo,
        DD, SS, sP, (size_t)DD * SS, sQK);

    // out = O@Wp^T + bp (fp32)
    mma_gemm<<<dim3(DD / 128, (BB * SS) / 128, 1), blk, GEMM_SMEM_BYTES>>>(
        Ohi, Olo, Wphi, Wplo, bp, 1.0f, out, nullptr, nullptr, DD, DD, 0, 0, 0);
}

// round 13
// speedup vs baseline: 3.0759x; 1.4580x over previous
#include <cuda_runtime.h>
#include <cuda_fp16.h>
#include <math.h>
#include <stdint.h>

#define BB 8
#define SS 2048
#define DD 768

// ---------------------------------------------------------------------------
// Scratch (device globals: allocation-free per harness rules)
// fp16 2-term scheme: A-side operands have hi+lo; B-side operands hi only.
// ---------------------------------------------------------------------------
__device__ __half g_xhi[BB * SS * DD], g_xlo[BB * SS * DD];
__device__ __half g_Wqh[DD * DD], g_Wkh[DD * DD], g_Wvh[DD * DD], g_Wph[DD * DD];
__device__ __half g_Qhi[BB * SS * DD], g_Qlo[BB * SS * DD];
__device__ __half g_Kh[BB * SS * DD];
__device__ __half g_Vth[BB * DD * SS];
__device__ float  g_P[(size_t)BB * SS * SS];
__device__ __half g_Phi[(size_t)BB * SS * SS], g_Plo[(size_t)BB * SS * SS];
__device__ __half g_Ohi[BB * SS * DD], g_Olo[BB * SS * DD];

// ---------------------------------------------------------------------------
// Portable PTX helpers
// ---------------------------------------------------------------------------
__device__ __forceinline__ uint32_t smem_to_u32(const void* p) {
    uint32_t a;
    asm("{ .reg .u64 t; cvta.to.shared.u64 t, %1; cvt.u32.u64 %0, t; }"
        : "=r"(a) : "l"(p));
    return a;
}

#define CP_ASYNC16(saddr, gaddr) \
    asm volatile("cp.async.cg.shared.global [%0], [%1], 16;" :: "r"(saddr), "l"(gaddr))
#define CP_COMMIT() asm volatile("cp.async.commit_group;" ::: "memory")
#define CP_WAIT(N)  asm volatile("cp.async.wait_group %0;" :: "n"(N) : "memory")

__device__ __forceinline__ void ldm_x4(uint32_t* r, uint32_t addr) {
    asm volatile("ldmatrix.sync.aligned.m8n8.x4.shared.b16 {%0,%1,%2,%3}, [%4];"
                 : "=r"(r[0]), "=r"(r[1]), "=r"(r[2]), "=r"(r[3]) : "r"(addr));
}

__device__ __forceinline__ void mma_f16(float* c, const uint32_t* a,
                                        uint32_t b0, uint32_t b1) {
    asm volatile(
        "mma.sync.aligned.m16n8k16.row.col.f32.f16.f16.f32 "
        "{%0,%1,%2,%3}, {%4,%5,%6,%7}, {%8,%9}, {%0,%1,%2,%3};"
        : "+f"(c[0]), "+f"(c[1]), "+f"(c[2]), "+f"(c[3])
        : "r"(a[0]), "r"(a[1]), "r"(a[2]), "r"(a[3]), "r"(b0), "r"(b1));
}

__device__ __forceinline__ uint32_t pack_h2(float a, float b) {
    __half2 t = __floats2half2_rn(a, b);
    return *reinterpret_cast<uint32_t*>(&t);
}

// ---------------------------------------------------------------------------
// GEMM machinery: 256 thr, 8 warps, warp 32x64, 128x128 tile, BK=32,
// double-buffered cp.async, one sync per chunk, 2 CTAs/SM.
// Stage = 3 matrices (Ah, Al, Bh).
// ---------------------------------------------------------------------------
#define ROWB 80                      // smem row pitch (64B data + 16B pad)
#define MATB (128 * ROWB)            // 10240 B per matrix tile
#define STGB (3 * MATB)              // 30720 B per stage
#define GEMM_SMEM_BYTES 66560        // max(2*STGB, 128x130 f32 transpose)

// Full K-loop; no trailing barrier (callers reusing smem must sync).
__device__ __forceinline__ void gemm_mainloop(
    uint32_t sb, int tid,
    const __half* Ahi, const __half* Alo, const __half* Bh,
    int bm, int bn, int K, float (*acc)[8][4])
{
    const int wid = tid >> 5;
    const int lid = tid & 31;
    const int wm = (wid & 3) << 5;
    const int wn = (wid >> 2) << 6;

    const int grow = tid >> 1;
    const int ghalf = (tid & 1) << 4;
    const uint32_t soff = grow * ROWB + ((tid & 1) << 5);

    auto issue_stage = [&](int c, int stg) {
        const int k0 = c << 5;
        const uint32_t s0 = sb + stg * STGB + soff;
        const __half* gA  = Ahi + (size_t)(bm + grow) * K + k0 + ghalf;
        const __half* gAl = Alo + (size_t)(bm + grow) * K + k0 + ghalf;
        const __half* gB  = Bh  + (size_t)(bn + grow) * K + k0 + ghalf;
        CP_ASYNC16(s0 + 0 * MATB,      gA);
        CP_ASYNC16(s0 + 0 * MATB + 16, gA + 8);
        CP_ASYNC16(s0 + 1 * MATB,      gAl);
        CP_ASYNC16(s0 + 1 * MATB + 16, gAl + 8);
        CP_ASYNC16(s0 + 2 * MATB,      gB);
        CP_ASYNC16(s0 + 2 * MATB + 16, gB + 8);
    };

    const uint32_t aLane = (uint32_t)(wm + (lid & 15)) * ROWB + ((lid >> 4) << 4);
    const uint32_t bLane = (uint32_t)(wn + (lid & 7) + ((lid >> 4) << 3)) * ROWB
                           + (((lid >> 3) & 1) << 4);

    const int nch = K >> 5;
    issue_stage(0, 0);
    CP_COMMIT();

    for (int c = 0; c < nch; c++) {
        CP_WAIT(0);
        __syncthreads();   // stage-c data visible + prev slot drained
        if (c + 1 < nch) {
            issue_stage(c + 1, (c + 1) & 1);
            CP_COMMIT();
        }

        const uint32_t stg = sb + (c & 1) * STGB;
        #pragma unroll
        for (int ks = 0; ks < 2; ks++) {
            const uint32_t kb = ks << 5;
            uint32_t aH[2][4], aL[2][4], bF[4][4];
            #pragma unroll
            for (int mt = 0; mt < 2; mt++)
                ldm_x4(aH[mt], stg + 0 * MATB + aLane + mt * (16 * ROWB) + kb);
            #pragma unroll
            for (int mt = 0; mt < 2; mt++)
                ldm_x4(aL[mt], stg + 1 * MATB + aLane + mt * (16 * ROWB) + kb);
            #pragma unroll
            for (int g = 0; g < 4; g++)
                ldm_x4(bF[g], stg + 2 * MATB + bLane + g * (16 * ROWB) + kb);
            // hh
            #pragma unroll
            for (int mt = 0; mt < 2; mt++)
                #pragma unroll
                for (int g = 0; g < 4; g++) {
                    mma_f16(acc[mt][2 * g],     aH[mt], bF[g][0], bF[g][1]);
                    mma_f16(acc[mt][2 * g + 1], aH[mt], bF[g][2], bF[g][3]);
                }
            // lh
            #pragma unroll
            for (int mt = 0; mt < 2; mt++)
                #pragma unroll
                for (int g = 0; g < 4; g++) {
                    mma_f16(acc[mt][2 * g],     aL[mt], bF[g][0], bF[g][1]);
                    mma_f16(acc[mt][2 * g + 1], aL[mt], bF[g][2], bF[g][3]);
                }
        }
    }
}

// ---------------------------------------------------------------------------
// Generic GEMM (NT): C = alpha*(A @ B^T) + bias.
// Outputs: fp32 Cf and/or fp16 hi/lo pair (Chi,Clo).
// ---------------------------------------------------------------------------
__global__ __launch_bounds__(256, 2) void mma_gemm(
    const __half* __restrict__ Ahi, const __half* __restrict__ Alo,
    const __half* __restrict__ Bh,
    const float* __restrict__ bias, float alpha,
    float* __restrict__ Cf,
    __half* __restrict__ Chi, __half* __restrict__ Clo,
    int ldc, int K, size_t strA, size_t strB, size_t strC)
{
    extern __shared__ char smem[];
    const uint32_t sb = smem_to_u32(smem);
    const int tid = threadIdx.x;
    const int wid = tid >> 5;
    const int lid = tid & 31;
    const int bm = blockIdx.y << 7;
    const int bn = blockIdx.x << 7;
    const int wm = (wid & 3) << 5;
    const int wn = (wid >> 2) << 6;

    float acc[2][8][4];
    #pragma unroll
    for (int i = 0; i < 2; i++)
        #pragma unroll
        for (int j = 0; j < 8; j++)
            #pragma unroll
            for (int q = 0; q < 4; q++) acc[i][j][q] = 0.0f;

    gemm_mainloop(sb, tid, Ahi + blockIdx.z * strA, Alo + blockIdx.z * strA,
                  Bh + blockIdx.z * strB, bm, bn, K, acc);

    const int r0 = lid >> 2;
    const int cq = (lid & 3) << 1;
    #pragma unroll
    for (int mt = 0; mt < 2; mt++) {
        #pragma unroll
        for (int half_ = 0; half_ < 2; half_++) {
            const int row = bm + wm + mt * 16 + r0 + half_ * 8;
            const size_t base = blockIdx.z * strC + (size_t)row * ldc + bn + wn;
            #pragma unroll
            for (int nt = 0; nt < 8; nt++) {
                const int col = wn + nt * 8 + cq;
                float v0 = acc[mt][nt][half_ * 2]     * alpha;
                float v1 = acc[mt][nt][half_ * 2 + 1] * alpha;
                if (bias) {
                    v0 += __ldg(bias + bn + col);
                    v1 += __ldg(bias + bn + col + 1);
                }
                if (Cf)
                    __stcs(reinterpret_cast<float2*>(Cf + base + nt * 8 + cq),
                           make_float2(v0, v1));
                if (Chi) {
                    const __half h0 = __float2half_rn(v0);
                    const __half h1 = __float2half_rn(v1);
                    const float l0 = v0 - __half2float(h0);
                    const float l1 = v1 - __half2float(h1);
                    *reinterpret_cast<uint32_t*>(Chi + base + nt * 8 + cq) =
                        pack_h2(v0, v1);
                    *reinterpret_cast<uint32_t*>(Clo + base + nt * 8 + cq) =
                        pack_h2(l0, l1);
                    (void)h0; (void)h1;
                }
            }
        }
    }
}

// ---------------------------------------------------------------------------
// Fused QKV projection: z=0 -> Q(hi/lo), z=1 -> K(hi only),
// z=2 -> V emitted TRANSPOSED as Vt[b][d][s] (hi only) via smem transpose.
// grid = (DD/128, BB*SS/128, 3)
// ---------------------------------------------------------------------------
__global__ __launch_bounds__(256, 2) void proj_qkv(
    const __half* __restrict__ xhi, const __half* __restrict__ xlo,
    const __half* __restrict__ Wqh, const __half* __restrict__ Wkh,
    const __half* __restrict__ Wvh,
    const float* __restrict__ bq, const float* __restrict__ bk,
    const float* __restrict__ bv,
    __half* __restrict__ Qhi, __half* __restrict__ Qlo,
    __half* __restrict__ Kh, __half* __restrict__ Vth)
{
    extern __shared__ char smem[];
    const uint32_t sb = smem_to_u32(smem);
    const int tid = threadIdx.x;
    const int wid = tid >> 5;
    const int lid = tid & 31;
    const int bm = blockIdx.y << 7;
    const int bn = blockIdx.x << 7;
    const int wm = (wid & 3) << 5;
    const int wn = (wid >> 2) << 6;
    const int z = blockIdx.z;

    const __half* Bh  = (z == 0) ? Wqh : (z == 1) ? Wkh : Wvh;
    const float* bias = (z == 0) ? bq  : (z == 1) ? bk  : bv;

    float acc[2][8][4];
    #pragma unroll
    for (int i = 0; i < 2; i++)
        #pragma unroll
        for (int j = 0; j < 8; j++)
            #pragma unroll
            for (int q = 0; q < 4; q++) acc[i][j][q] = 0.0f;

    gemm_mainloop(sb, tid, xhi, xlo, Bh, bm, bn, DD, acc);

    const int r0 = lid >> 2;
    const int cq = (lid & 3) << 1;

    if (z == 0) {
        #pragma unroll
        for (int mt = 0; mt < 2; mt++) {
            #pragma unroll
            for (int half_ = 0; half_ < 2; half_++) {
                const int row = bm + wm + mt * 16 + r0 + half_ * 8;
                const size_t base = (size_t)row * DD + bn + wn;
                #pragma unroll
                for (int nt = 0; nt < 8; nt++) {
                    const int col = wn + nt * 8 + cq;
                    float v0 = acc[mt][nt][half_ * 2]     + __ldg(bias + bn + col);
                    float v1 = acc[mt][nt][half_ * 2 + 1] + __ldg(bias + bn + col + 1);
                    const __half h0 = __float2half_rn(v0);
                    const __half h1 = __float2half_rn(v1);
                    *reinterpret_cast<uint32_t*>(Qhi + base + nt * 8 + cq) =
                        pack_h2(v0, v1);
                    *reinterpret_cast<uint32_t*>(Qlo + base + nt * 8 + cq) =
                        pack_h2(v0 - __half2float(h0), v1 - __half2float(h1));
                }
            }
        }
    } else if (z == 1) {
        #pragma unroll
        for (int mt = 0; mt < 2; mt++) {
            #pragma unroll
            for (int half_ = 0; half_ < 2; half_++) {
                const int row = bm + wm + mt * 16 + r0 + half_ * 8;
                const size_t base = (size_t)row * DD + bn + wn;
                #pragma unroll
                for (int nt = 0; nt < 8; nt++) {
                    const int col = wn + nt * 8 + cq;
                    float v0 = acc[mt][nt][half_ * 2]     + __ldg(bias + bn + col);
                    float v1 = acc[mt][nt][half_ * 2 + 1] + __ldg(bias + bn + col + 1);
                    *reinterpret_cast<uint32_t*>(Kh + base + nt * 8 + cq) =
                        pack_h2(v0, v1);
                }
            }
        }
    } else {
        // barrier before smem reuse (mainloop has no trailing sync)
        __syncthreads();
        float* sf = reinterpret_cast<float*>(smem);
        #pragma unroll
        for (int mt = 0; mt < 2; mt++) {
            #pragma unroll
            for (int half_ = 0; half_ < 2; half_++) {
                const int rloc = wm + mt * 16 + r0 + half_ * 8;
                #pragma unroll
                for (int nt = 0; nt < 8; nt++) {
                    const int col = wn + nt * 8 + cq;
                    float v0 = acc[mt][nt][half_ * 2]     + __ldg(bias + bn + col);
                    float v1 = acc[mt][nt][half_ * 2 + 1] + __ldg(bias + bn + col + 1);
                    sf[(size_t)col * 130 + rloc]       = v0;
                    sf[(size_t)(col + 1) * 130 + rloc] = v1;
                }
            }
        }
        __syncthreads();
        const int b = bm >> 11;
        const int s_base = bm & (SS - 1);
        const int d = tid >> 1;
        const int sc = (tid & 1) << 6;
        const float* srow = sf + (size_t)d * 130 + sc;
        __half* th = Vth + ((size_t)b * DD + bn + d) * SS + s_base + sc;
        #pragma unroll
        for (int j = 0; j < 64; j += 8) {
            uint4 ph;
            uint32_t* php = reinterpret_cast<uint32_t*>(&ph);
            #pragma unroll
            for (int p = 0; p < 4; p++)
                php[p] = pack_h2(srow[j + 2 * p], srow[j + 2 * p + 1]);
            *reinterpret_cast<uint4*>(th + j) = ph;
        }
    }
}

// ---------------------------------------------------------------------------
// fp32 -> fp16 hi/lo split (for x)
// ---------------------------------------------------------------------------
__global__ void split_kernel(const float* __restrict__ in,
                             __half* __restrict__ hi,
                             __half* __restrict__ lo, int n4)
{
    const int i = blockIdx.x * blockDim.x + threadIdx.x;
    if (i >= n4) return;
    const float4 v = reinterpret_cast<const float4*>(in)[i];
    float f[4] = {v.x, v.y, v.z, v.w};
    float l[4];
    #pragma unroll
    for (int j = 0; j < 4; j++) {
        const __half h = __float2half_rn(f[j]);
        l[j] = f[j] - __half2float(h);
    }
    reinterpret_cast<uint2*>(hi)[i] =
        make_uint2(pack_h2(f[0], f[1]), pack_h2(f[2], f[3]));
    reinterpret_cast<uint2*>(lo)[i] =
        make_uint2(pack_h2(l[0], l[1]), pack_h2(l[2], l[3]));
}

// 4 weight matrices -> fp16 (hi only) in one launch
__global__ void wconv_kernel(const float* __restrict__ Wq, const float* __restrict__ Wk,
                             const float* __restrict__ Wv, const float* __restrict__ Wp,
                             __half* __restrict__ qh, __half* __restrict__ kh,
                             __half* __restrict__ vh, __half* __restrict__ ph,
                             int n4)
{
    const int i = blockIdx.x * blockDim.x + threadIdx.x;
    if (i >= n4) return;
    const int m = blockIdx.y;
    const float* in = (m == 0) ? Wq : (m == 1) ? Wk : (m == 2) ? Wv : Wp;
    __half* hi = (m == 0) ? qh : (m == 1) ? kh : (m == 2) ? vh : ph;
    const float4 v = reinterpret_cast<const float4*>(in)[i];
    reinterpret_cast<uint2*>(hi)[i] =
        make_uint2(pack_h2(v.x, v.y), pack_h2(v.z, v.w));
}

// ---------------------------------------------------------------------------
// Row softmax over S=2048, emitting fp16 hi/lo.
// ---------------------------------------------------------------------------
__global__ __launch_bounds__(256) void softmax_split(const float* __restrict__ P,
                                                     __half* __restrict__ Phi,
                                                     __half* __restrict__ Plo)
{
    const size_t rowoff = (size_t)blockIdx.x * SS;
    const float* row = P + rowoff;
    const int tid = threadIdx.x;
    __shared__ float red[8];

    float4 v0 = __ldcs(((const float4*)row) + tid);
    float4 v1 = __ldcs(((const float4*)row) + tid + 256);

    float m = fmaxf(fmaxf(fmaxf(v0.x, v0.y), fmaxf(v0.z, v0.w)),
                    fmaxf(fmaxf(v1.x, v1.y), fmaxf(v1.z, v1.w)));
    #pragma unroll
    for (int o = 16; o > 0; o >>= 1)
        m = fmaxf(m, __shfl_xor_sync(0xffffffffu, m, o));
    if ((tid & 31) == 0) red[tid >> 5] = m;
    __syncthreads();
    float bmax = red[0];
    #pragma unroll
    for (int i = 1; i < 8; i++) bmax = fmaxf(bmax, red[i]);
    __syncthreads();

    v0.x = __expf(v0.x - bmax); v0.y = __expf(v0.y - bmax);
    v0.z = __expf(v0.z - bmax); v0.w = __expf(v0.w - bmax);
    v1.x = __expf(v1.x - bmax); v1.y = __expf(v1.y - bmax);
    v1.z = __expf(v1.z - bmax); v1.w = __expf(v1.w - bmax);

    float s = v0.x + v0.y + v0.z + v0.w + v1.x + v1.y + v1.z + v1.w;
    #pragma unroll
    for (int o = 16; o > 0; o >>= 1)
        s += __shfl_xor_sync(0xffffffffu, s, o);
    if ((tid & 31) == 0) red[tid >> 5] = s;
    __syncthreads();
    float total = 0.0f;
    #pragma unroll
    for (int i = 0; i < 8; i++) total += red[i];
    const float inv = __frcp_rn(total);

    float f[8] = {v0.x * inv, v0.y * inv, v0.z * inv, v0.w * inv,
                  v1.x * inv, v1.y * inv, v1.z * inv, v1.w * inv};
    float l[8];
    #pragma unroll
    for (int j = 0; j < 8; j++) {
        const __half h = __float2half_rn(f[j]);
        l[j] = f[j] - __half2float(h);
    }
    uint2* ph = reinterpret_cast<uint2*>(Phi + rowoff);
    uint2* pl = reinterpret_cast<uint2*>(Plo + rowoff);
    ph[tid]       = make_uint2(pack_h2(f[0], f[1]), pack_h2(f[2], f[3]));
    ph[tid + 256] = make_uint2(pack_h2(f[4], f[5]), pack_h2(f[6], f[7]));
    pl[tid]       = make_uint2(pack_h2(l[0], l[1]), pack_h2(l[2], l[3]));
    pl[tid + 256] = make_uint2(pack_h2(l[4], l[5]), pack_h2(l[6], l[7]));
}

// ---------------------------------------------------------------------------
extern "C" void kernel_launch(void* const* d_in, const int* in_sizes, int n_in,
                              void* d_out, int out_size)
{
    const float* x  = (const float*)d_in[0];
    const float* Wq = (const float*)d_in[1];
    const float* bq = (const float*)d_in[2];
    const float* Wk = (const float*)d_in[3];
    const float* bk = (const float*)d_in[4];
    const float* Wv = (const float*)d_in[5];
    const float* bv = (const float*)d_in[6];
    const float* Wp = (const float*)d_in[7];
    const float* bp = (const float*)d_in[8];
    float* out = (float*)d_out;

    __half *xhi, *xlo, *Wqh, *Wkh, *Wvh, *Wph;
    __half *Qhi, *Qlo, *Kh, *Vth, *Phi, *Plo, *Ohi, *Olo;
    float *P;
    cudaGetSymbolAddress((void**)&xhi, g_xhi); cudaGetSymbolAddress((void**)&xlo, g_xlo);
    cudaGetSymbolAddress((void**)&Wqh, g_Wqh); cudaGetSymbolAddress((void**)&Wkh, g_Wkh);
    cudaGetSymbolAddress((void**)&Wvh, g_Wvh); cudaGetSymbolAddress((void**)&Wph, g_Wph);
    cudaGetSymbolAddress((void**)&Qhi, g_Qhi); cudaGetSymbolAddress((void**)&Qlo, g_Qlo);
    cudaGetSymbolAddress((void**)&Kh, g_Kh);   cudaGetSymbolAddress((void**)&Vth, g_Vth);
    cudaGetSymbolAddress((void**)&P, g_P);
    cudaGetSymbolAddress((void**)&Phi, g_Phi); cudaGetSymbolAddress((void**)&Plo, g_Plo);
    cudaGetSymbolAddress((void**)&Ohi, g_Ohi); cudaGetSymbolAddress((void**)&Olo, g_Olo);

    cudaFuncSetAttribute(mma_gemm, cudaFuncAttributeMaxDynamicSharedMemorySize,
                         GEMM_SMEM_BYTES);
    cudaFuncSetAttribute(proj_qkv, cudaFuncAttributeMaxDynamicSharedMemorySize,
                         GEMM_SMEM_BYTES);

    const float alpha = 1.0f / sqrtf((float)DD);
    const size_t sQK = (size_t)SS * DD;
    const size_t sP  = (size_t)SS * SS;

    // splits / converts
    {
        const int n4x = BB * SS * DD / 4;
        split_kernel<<<(n4x + 255) / 256, 256>>>(x, xhi, xlo, n4x);
        const int n4w = DD * DD / 4;
        wconv_kernel<<<dim3((n4w + 255) / 256, 4), 256>>>(
            Wq, Wk, Wv, Wp, Wqh, Wkh, Wvh, Wph, n4w);
    }

    const dim3 blk(256);

    // fused Q/K/V projections (K hi-only, V transposed hi-only)
    proj_qkv<<<dim3(DD / 128, (BB * SS) / 128, 3), blk, GEMM_SMEM_BYTES>>>(
        xhi, xlo, Wqh, Wkh, Wvh, bq, bk, bv, Qhi, Qlo, Kh, Vth);

    // P = (Q@K^T)/sqrt(D)  (fp32)
    mma_gemm<<<dim3(SS / 128, SS / 128, BB), blk, GEMM_SMEM_BYTES>>>(
        Qhi, Qlo, Kh, nullptr, alpha, P, nullptr, nullptr,
        SS, DD, sQK, sQK, sP);

    // softmax rows -> fp16 hi/lo
    softmax_split<<<BB * SS, 256>>>(P, Phi, Plo);

    // O = P@V  (NT against Vt[D,S]; emit fp16 hi/lo)
    mma_gemm<<<dim3(DD / 128, SS / 128, BB), blk, GEMM_SMEM_BYTES>>>(
        Phi, Plo, Vth, nullptr, 1.0f, nullptr, Ohi, Olo,
        DD, SS, sP, (size_t)DD * SS, sQK);

    // out = O@Wp^T + bp  (fp32)
    mma_gemm<<<dim3(DD / 128, (BB * SS) / 128, 1), blk, GEMM_SMEM_BYTES>>>(
        Ohi, Olo, Wph, bp, 1.0f, out, nullptr, nullptr, DD, DD, 0, 0, 0);
}

// round 14
// speedup vs baseline: 3.1396x; 1.0207x over previous
#include <cuda_runtime.h>
#include <cuda_fp16.h>
#include <math.h>
#include <stdint.h>

#define BB 8
#define SS 2048
#define DD 768

// ---------------------------------------------------------------------------
// Scratch (device globals: allocation-free per harness rules)
// Full single-fp16 scheme: every GEMM operand is one fp16 tensor.
// ---------------------------------------------------------------------------
__device__ __half g_x16[BB * SS * DD];
__device__ __half g_Wqh[DD * DD], g_Wkh[DD * DD], g_Wvh[DD * DD], g_Wph[DD * DD];
__device__ __half g_Q16[BB * SS * DD];
__device__ __half g_K16[BB * SS * DD];
__device__ __half g_Vt16[BB * DD * SS];
__device__ float  g_P[(size_t)BB * SS * SS];
__device__ __half g_P16[(size_t)BB * SS * SS];
__device__ __half g_O16[BB * SS * DD];

// ---------------------------------------------------------------------------
// Portable PTX helpers
// ---------------------------------------------------------------------------
__device__ __forceinline__ uint32_t smem_to_u32(const void* p) {
    uint32_t a;
    asm("{ .reg .u64 t; cvta.to.shared.u64 t, %1; cvt.u32.u64 %0, t; }"
        : "=r"(a) : "l"(p));
    return a;
}

#define CP_ASYNC16(saddr, gaddr) \
    asm volatile("cp.async.cg.shared.global [%0], [%1], 16;" :: "r"(saddr), "l"(gaddr))
#define CP_COMMIT() asm volatile("cp.async.commit_group;" ::: "memory")
#define CP_WAIT(N)  asm volatile("cp.async.wait_group %0;" :: "n"(N) : "memory")

__device__ __forceinline__ void ldm_x4(uint32_t* r, uint32_t addr) {
    asm volatile("ldmatrix.sync.aligned.m8n8.x4.shared.b16 {%0,%1,%2,%3}, [%4];"
                 : "=r"(r[0]), "=r"(r[1]), "=r"(r[2]), "=r"(r[3]) : "r"(addr));
}

__device__ __forceinline__ void mma_f16(float* c, const uint32_t* a,
                                        uint32_t b0, uint32_t b1) {
    asm volatile(
        "mma.sync.aligned.m16n8k16.row.col.f32.f16.f16.f32 "
        "{%0,%1,%2,%3}, {%4,%5,%6,%7}, {%8,%9}, {%0,%1,%2,%3};"
        : "+f"(c[0]), "+f"(c[1]), "+f"(c[2]), "+f"(c[3])
        : "r"(a[0]), "r"(a[1]), "r"(a[2]), "r"(a[3]), "r"(b0), "r"(b1));
}

__device__ __forceinline__ uint32_t pack_h2(float a, float b) {
    __half2 t = __floats2half2_rn(a, b);
    return *reinterpret_cast<uint32_t*>(&t);
}

// ---------------------------------------------------------------------------
// GEMM machinery: 256 thr, 8 warps, warp 32x64, 128x128 tile, BK=32,
// double-buffered cp.async, one sync per chunk, 2 CTAs/SM.
// Stage = 2 matrices (A, B), single MMA pass.
// ---------------------------------------------------------------------------
#define ROWB 80                      // smem row pitch (64B data + 16B pad)
#define MATB (128 * ROWB)            // 10240 B per matrix tile
#define STGB (2 * MATB)              // 20480 B per stage
#define GEMM_SMEM_BYTES 66560        // max(2*STGB, 128x130 f32 transpose)

// Full K-loop; no trailing barrier (callers reusing smem must sync).
__device__ __forceinline__ void gemm_mainloop(
    uint32_t sb, int tid,
    const __half* A, const __half* B,
    int bm, int bn, int K, float (*acc)[8][4])
{
    const int wid = tid >> 5;
    const int lid = tid & 31;
    const int wm = (wid & 3) << 5;
    const int wn = (wid >> 2) << 6;

    const int grow = tid >> 1;
    const int ghalf = (tid & 1) << 4;
    const uint32_t soff = grow * ROWB + ((tid & 1) << 5);

    auto issue_stage = [&](int c, int stg) {
        const int k0 = c << 5;
        const uint32_t s0 = sb + stg * STGB + soff;
        const __half* gA = A + (size_t)(bm + grow) * K + k0 + ghalf;
        const __half* gB = B + (size_t)(bn + grow) * K + k0 + ghalf;
        CP_ASYNC16(s0 + 0 * MATB,      gA);
        CP_ASYNC16(s0 + 0 * MATB + 16, gA + 8);
        CP_ASYNC16(s0 + 1 * MATB,      gB);
        CP_ASYNC16(s0 + 1 * MATB + 16, gB + 8);
    };

    const uint32_t aLane = (uint32_t)(wm + (lid & 15)) * ROWB + ((lid >> 4) << 4);
    const uint32_t bLane = (uint32_t)(wn + (lid & 7) + ((lid >> 4) << 3)) * ROWB
                           + (((lid >> 3) & 1) << 4);

    const int nch = K >> 5;
    issue_stage(0, 0);
    CP_COMMIT();

    for (int c = 0; c < nch; c++) {
        CP_WAIT(0);
        __syncthreads();   // stage-c visible + prev slot drained
        if (c + 1 < nch) {
            issue_stage(c + 1, (c + 1) & 1);
            CP_COMMIT();
        }

        const uint32_t stg = sb + (c & 1) * STGB;
        #pragma unroll
        for (int ks = 0; ks < 2; ks++) {
            const uint32_t kb = ks << 5;
            uint32_t aF[2][4], bF[4][4];
            #pragma unroll
            for (int mt = 0; mt < 2; mt++)
                ldm_x4(aF[mt], stg + 0 * MATB + aLane + mt * (16 * ROWB) + kb);
            #pragma unroll
            for (int g = 0; g < 4; g++)
                ldm_x4(bF[g], stg + 1 * MATB + bLane + g * (16 * ROWB) + kb);
            #pragma unroll
            for (int mt = 0; mt < 2; mt++)
                #pragma unroll
                for (int g = 0; g < 4; g++) {
                    mma_f16(acc[mt][2 * g],     aF[mt], bF[g][0], bF[g][1]);
                    mma_f16(acc[mt][2 * g + 1], aF[mt], bF[g][2], bF[g][3]);
                }
        }
    }
}

// ---------------------------------------------------------------------------
// Generic GEMM (NT): C = alpha*(A @ B^T) + bias.
// Outputs: fp32 Cf and/or single fp16 Ch.
// ---------------------------------------------------------------------------
__global__ __launch_bounds__(256, 2) void mma_gemm(
    const __half* __restrict__ A, const __half* __restrict__ B,
    const float* __restrict__ bias, float alpha,
    float* __restrict__ Cf, __half* __restrict__ Ch,
    int ldc, int K, size_t strA, size_t strB, size_t strC)
{
    extern __shared__ char smem[];
    const uint32_t sb = smem_to_u32(smem);
    const int tid = threadIdx.x;
    const int wid = tid >> 5;
    const int lid = tid & 31;
    const int bm = blockIdx.y << 7;
    const int bn = blockIdx.x << 7;
    const int wm = (wid & 3) << 5;
    const int wn = (wid >> 2) << 6;

    float acc[2][8][4];
    #pragma unroll
    for (int i = 0; i < 2; i++)
        #pragma unroll
        for (int j = 0; j < 8; j++)
            #pragma unroll
            for (int q = 0; q < 4; q++) acc[i][j][q] = 0.0f;

    gemm_mainloop(sb, tid, A + blockIdx.z * strA, B + blockIdx.z * strB,
                  bm, bn, K, acc);

    const int r0 = lid >> 2;
    const int cq = (lid & 3) << 1;
    #pragma unroll
    for (int mt = 0; mt < 2; mt++) {
        #pragma unroll
        for (int half_ = 0; half_ < 2; half_++) {
            const int row = bm + wm + mt * 16 + r0 + half_ * 8;
            const size_t base = blockIdx.z * strC + (size_t)row * ldc + bn + wn;
            #pragma unroll
            for (int nt = 0; nt < 8; nt++) {
                const int col = wn + nt * 8 + cq;
                float v0 = acc[mt][nt][half_ * 2]     * alpha;
                float v1 = acc[mt][nt][half_ * 2 + 1] * alpha;
                if (bias) {
                    v0 += __ldg(bias + bn + col);
                    v1 += __ldg(bias + bn + col + 1);
                }
                if (Cf)
                    __stcs(reinterpret_cast<float2*>(Cf + base + nt * 8 + cq),
                           make_float2(v0, v1));
                if (Ch)
                    *reinterpret_cast<uint32_t*>(Ch + base + nt * 8 + cq) =
                        pack_h2(v0, v1);
            }
        }
    }
}

// ---------------------------------------------------------------------------
// Fused QKV projection: z=0 -> Q16, z=1 -> K16,
// z=2 -> V emitted TRANSPOSED as Vt16[b][d][s] via smem transpose.
// grid = (DD/128, BB*SS/128, 3)
// ---------------------------------------------------------------------------
__global__ __launch_bounds__(256, 2) void proj_qkv(
    const __half* __restrict__ x16,
    const __half* __restrict__ Wqh, const __half* __restrict__ Wkh,
    const __half* __restrict__ Wvh,
    const float* __restrict__ bq, const float* __restrict__ bk,
    const float* __restrict__ bv,
    __half* __restrict__ Q16, __half* __restrict__ K16,
    __half* __restrict__ Vt16)
{
    extern __shared__ char smem[];
    const uint32_t sb = smem_to_u32(smem);
    const int tid = threadIdx.x;
    const int wid = tid >> 5;
    const int lid = tid & 31;
    const int bm = blockIdx.y << 7;
    const int bn = blockIdx.x << 7;
    const int wm = (wid & 3) << 5;
    const int wn = (wid >> 2) << 6;
    const int z = blockIdx.z;

    const __half* Bh  = (z == 0) ? Wqh : (z == 1) ? Wkh : Wvh;
    const float* bias = (z == 0) ? bq  : (z == 1) ? bk  : bv;

    float acc[2][8][4];
    #pragma unroll
    for (int i = 0; i < 2; i++)
        #pragma unroll
        for (int j = 0; j < 8; j++)
            #pragma unroll
            for (int q = 0; q < 4; q++) acc[i][j][q] = 0.0f;

    gemm_mainloop(sb, tid, x16, Bh, bm, bn, DD, acc);

    const int r0 = lid >> 2;
    const int cq = (lid & 3) << 1;

    if (z < 2) {
        __half* Co = (z == 0) ? Q16 : K16;
        #pragma unroll
        for (int mt = 0; mt < 2; mt++) {
            #pragma unroll
            for (int half_ = 0; half_ < 2; half_++) {
                const int row = bm + wm + mt * 16 + r0 + half_ * 8;
                const size_t base = (size_t)row * DD + bn + wn;
                #pragma unroll
                for (int nt = 0; nt < 8; nt++) {
                    const int col = wn + nt * 8 + cq;
                    float v0 = acc[mt][nt][half_ * 2]     + __ldg(bias + bn + col);
                    float v1 = acc[mt][nt][half_ * 2 + 1] + __ldg(bias + bn + col + 1);
                    *reinterpret_cast<uint32_t*>(Co + base + nt * 8 + cq) =
                        pack_h2(v0, v1);
                }
            }
        }
    } else {
        // barrier before smem reuse (mainloop has no trailing sync)
        __syncthreads();
        float* sf = reinterpret_cast<float*>(smem);
        #pragma unroll
        for (int mt = 0; mt < 2; mt++) {
            #pragma unroll
            for (int half_ = 0; half_ < 2; half_++) {
                const int rloc = wm + mt * 16 + r0 + half_ * 8;
                #pragma unroll
                for (int nt = 0; nt < 8; nt++) {
                    const int col = wn + nt * 8 + cq;
                    float v0 = acc[mt][nt][half_ * 2]     + __ldg(bias + bn + col);
                    float v1 = acc[mt][nt][half_ * 2 + 1] + __ldg(bias + bn + col + 1);
                    sf[(size_t)col * 130 + rloc]       = v0;
                    sf[(size_t)(col + 1) * 130 + rloc] = v1;
                }
            }
        }
        __syncthreads();
        const int b = bm >> 11;
        const int s_base = bm & (SS - 1);
        const int d = tid >> 1;
        const int sc = (tid & 1) << 6;
        const float* srow = sf + (size_t)d * 130 + sc;
        __half* th = Vt16 + ((size_t)b * DD + bn + d) * SS + s_base + sc;
        #pragma unroll
        for (int j = 0; j < 64; j += 8) {
            uint4 ph;
            uint32_t* php = reinterpret_cast<uint32_t*>(&ph);
            #pragma unroll
            for (int p = 0; p < 4; p++)
                php[p] = pack_h2(srow[j + 2 * p], srow[j + 2 * p + 1]);
            *reinterpret_cast<uint4*>(th + j) = ph;
        }
    }
}

// ---------------------------------------------------------------------------
// fp32 -> fp16 converts
// ---------------------------------------------------------------------------
__global__ void xconv_kernel(const float* __restrict__ in,
                             __half* __restrict__ o16, int n4)
{
    const int i = blockIdx.x * blockDim.x + threadIdx.x;
    if (i >= n4) return;
    const float4 v = reinterpret_cast<const float4*>(in)[i];
    reinterpret_cast<uint2*>(o16)[i] =
        make_uint2(pack_h2(v.x, v.y), pack_h2(v.z, v.w));
}

__global__ void wconv_kernel(const float* __restrict__ Wq, const float* __restrict__ Wk,
                             const float* __restrict__ Wv, const float* __restrict__ Wp,
                             __half* __restrict__ qh, __half* __restrict__ kh,
                             __half* __restrict__ vh, __half* __restrict__ ph,
                             int n4)
{
    const int i = blockIdx.x * blockDim.x + threadIdx.x;
    if (i >= n4) return;
    const int m = blockIdx.y;
    const float* in = (m == 0) ? Wq : (m == 1) ? Wk : (m == 2) ? Wv : Wp;
    __half* hi = (m == 0) ? qh : (m == 1) ? kh : (m == 2) ? vh : ph;
    const float4 v = reinterpret_cast<const float4*>(in)[i];
    reinterpret_cast<uint2*>(hi)[i] =
        make_uint2(pack_h2(v.x, v.y), pack_h2(v.z, v.w));
}

// ---------------------------------------------------------------------------
// Row softmax over S=2048, emitting single fp16.
// ---------------------------------------------------------------------------
__global__ __launch_bounds__(256) void softmax16(const float* __restrict__ P,
                                                 __half* __restrict__ P16)
{
    const size_t rowoff = (size_t)blockIdx.x * SS;
    const float* row = P + rowoff;
    const int tid = threadIdx.x;
    __shared__ float red[8];

    float4 v0 = __ldcs(((const float4*)row) + tid);
    float4 v1 = __ldcs(((const float4*)row) + tid + 256);

    float m = fmaxf(fmaxf(fmaxf(v0.x, v0.y), fmaxf(v0.z, v0.w)),
                    fmaxf(fmaxf(v1.x, v1.y), fmaxf(v1.z, v1.w)));
    #pragma unroll
    for (int o = 16; o > 0; o >>= 1)
        m = fmaxf(m, __shfl_xor_sync(0xffffffffu, m, o));
    if ((tid & 31) == 0) red[tid >> 5] = m;
    __syncthreads();
    float bmax = red[0];
    #pragma unroll
    for (int i = 1; i < 8; i++) bmax = fmaxf(bmax, red[i]);
    __syncthreads();

    v0.x = __expf(v0.x - bmax); v0.y = __expf(v0.y - bmax);
    v0.z = __expf(v0.z - bmax); v0.w = __expf(v0.w - bmax);
    v1.x = __expf(v1.x - bmax); v1.y = __expf(v1.y - bmax);
    v1.z = __expf(v1.z - bmax); v1.w = __expf(v1.w - bmax);

    float s = v0.x + v0.y + v0.z + v0.w + v1.x + v1.y + v1.z + v1.w;
    #pragma unroll
    for (int o = 16; o > 0; o >>= 1)
        s += __shfl_xor_sync(0xffffffffu, s, o);
    if ((tid & 31) == 0) red[tid >> 5] = s;
    __syncthreads();
    float total = 0.0f;
    #pragma unroll
    for (int i = 0; i < 8; i++) total += red[i];
    const float inv = __frcp_rn(total);

    uint2* ph = reinterpret_cast<uint2*>(P16 + rowoff);
    ph[tid]       = make_uint2(pack_h2(v0.x * inv, v0.y * inv),
                               pack_h2(v0.z * inv, v0.w * inv));
    ph[tid + 256] = make_uint2(pack_h2(v1.x * inv, v1.y * inv),
                               pack_h2(v1.z * inv, v1.w * inv));
}

// ---------------------------------------------------------------------------
extern "C" void kernel_launch(void* const* d_in, const int* in_sizes, int n_in,
                              void* d_out, int out_size)
{
    const float* x  = (const float*)d_in[0];
    const float* Wq = (const float*)d_in[1];
    const float* bq = (const float*)d_in[2];
    const float* Wk = (const float*)d_in[3];
    const float* bk = (const float*)d_in[4];
    const float* Wv = (const float*)d_in[5];
    const float* bv = (const float*)d_in[6];
    const float* Wp = (const float*)d_in[7];
    const float* bp = (const float*)d_in[8];
    float* out = (float*)d_out;

    __half *x16, *Wqh, *Wkh, *Wvh, *Wph, *Q16, *K16, *Vt16, *P16, *O16;
    float *P;
    cudaGetSymbolAddress((void**)&x16, g_x16);
    cudaGetSymbolAddress((void**)&Wqh, g_Wqh); cudaGetSymbolAddress((void**)&Wkh, g_Wkh);
    cudaGetSymbolAddress((void**)&Wvh, g_Wvh); cudaGetSymbolAddress((void**)&Wph, g_Wph);
    cudaGetSymbolAddress((void**)&Q16, g_Q16); cudaGetSymbolAddress((void**)&K16, g_K16);
    cudaGetSymbolAddress((void**)&Vt16, g_Vt16);
    cudaGetSymbolAddress((void**)&P, g_P);     cudaGetSymbolAddress((void**)&P16, g_P16);
    cudaGetSymbolAddress((void**)&O16, g_O16);

    cudaFuncSetAttribute(mma_gemm, cudaFuncAttributeMaxDynamicSharedMemorySize,
                         GEMM_SMEM_BYTES);
    cudaFuncSetAttribute(proj_qkv, cudaFuncAttributeMaxDynamicSharedMemorySize,
                         GEMM_SMEM_BYTES);

    const float alpha = 1.0f / sqrtf((float)DD);
    const size_t sQK = (size_t)SS * DD;
    const size_t sP  = (size_t)SS * SS;

    // converts
    {
        const int n4x = BB * SS * DD / 4;
        xconv_kernel<<<(n4x + 255) / 256, 256>>>(x, x16, n4x);
        const int n4w = DD * DD / 4;
        wconv_kernel<<<dim3((n4w + 255) / 256, 4), 256>>>(
            Wq, Wk, Wv, Wp, Wqh, Wkh, Wvh, Wph, n4w);
    }

    const dim3 blk(256);

    // fused Q/K/V projections (V transposed)
    proj_qkv<<<dim3(DD / 128, (BB * SS) / 128, 3), blk, GEMM_SMEM_BYTES>>>(
        x16, Wqh, Wkh, Wvh, bq, bk, bv, Q16, K16, Vt16);

    // P = (Q@K^T)/sqrt(D)  (fp32)
    mma_gemm<<<dim3(SS / 128, SS / 128, BB), blk, GEMM_SMEM_BYTES>>>(
        Q16, K16, nullptr, alpha, P, nullptr, SS, DD, sQK, sQK, sP);

    // softmax rows -> fp16
    softmax16<<<BB * SS, 256>>>(P, P16);

    // O = P@V  (NT against Vt[D,S])
    mma_gemm<<<dim3(DD / 128, SS / 128, BB), blk, GEMM_SMEM_BYTES>>>(
        P16, Vt16, nullptr, 1.0f, nullptr, O16, DD, SS, sP, (size_t)DD * SS, sQK);

    // out = O@Wp^T + bp  (fp32)
    mma_gemm<<<dim3(DD / 128, (BB * SS) / 128, 1), blk, GEMM_SMEM_BYTES>>>(
        O16, Wph, bp, 1.0f, out, nullptr, DD, DD, 0, 0, 0);
}